// round 9
// baseline (speedup 1.0000x reference)
#include <cuda_runtime.h>
#include <cuda_bf16.h>
#include <cstdint>
#include <cstddef>

// Problem constants
#define N_ROWS   16384
#define D_DIM    512
#define K_CENT   2048
#define EMA      0.99f
#define GAMMAF   1.0f
#define EPSF     1e-8f
#define DELTA    1.5e-2f
#define ROWS_PER_BLK 16
#define NBLK_SM  (N_ROWS / ROWS_PER_BLK)   // 1024
#define NCHUNK   4
#define BLK_PER_CHUNK (NBLK_SM / NCHUNK)   // 256
#define MTILE_PER_CHUNK 32                 // 32 * 128 = 4096 rows per chunk

// Output layout (float32, concatenated in reference return order)
#define OFF_Q    ((size_t)0)
#define OFF_LOSS ((size_t)8388608)
#define OFF_IDX  ((size_t)41943040)
#define OFF_CB   ((size_t)41959424)
#define OFF_CNT  ((size_t)43008000)

// ---------------- scratch (static device memory) -----------------------------
__device__ __align__(16) __nv_bfloat16 g_simh[(size_t)N_ROWS * K_CENT];   // 67 MB
__device__ float g_div_part[(size_t)NBLK_SM * K_CENT];    // 8 MB
__device__ float g_div2[16 * K_CENT];
__device__ float g_h_part[NBLK_SM];
__device__ int   g_counts[K_CENT];
__device__ float g_loss;
__device__ int   g_cand[(size_t)N_ROWS * 32];             // 2 MB
__device__ int   g_ncand[N_ROWS];
__device__ __align__(16) __nv_bfloat16 g_Abf[(size_t)N_ROWS * D_DIM];  // 16.8 MB
__device__ __align__(16) __nv_bfloat16 g_Bbf[(size_t)K_CENT * D_DIM];  // 2 MB

__device__ __forceinline__ uint32_t smem_u32(const void* p) {
    uint32_t a;
    asm("{ .reg .u64 t; cvta.to.shared.u64 t, %1; cvt.u32.u64 %0, t; }" : "=r"(a) : "l"(p));
    return a;
}

// ---------------- kernel: fp32 -> bf16 convert --------------------------------
__global__ __launch_bounds__(256)
void vq_convert(const float* __restrict__ A, const float* __restrict__ B) {
    const size_t NA4 = (size_t)N_ROWS * D_DIM / 4;   // 2097152
    const size_t NB4 = (size_t)K_CENT * D_DIM / 4;   // 262144
    size_t i = (size_t)blockIdx.x * 256 + threadIdx.x;
    if (i >= NA4 + NB4) return;
    const bool isA = (i < NA4);
    const float4 x = isA ? ((const float4*)A)[i] : ((const float4*)B)[i - NA4];
    __nv_bfloat162 lo = __floats2bfloat162_rn(x.x, x.y);
    __nv_bfloat162 hi = __floats2bfloat162_rn(x.z, x.w);
    size_t e = (isA ? i : (i - NA4));
    __nv_bfloat162* d = (__nv_bfloat162*)(isA ? g_Abf : g_Bbf);
    d[e * 2]     = lo;
    d[e * 2 + 1] = hi;
}

// ---------------- kernel: reset counters --------------------------------------
__global__ __launch_bounds__(256)
void vq_init() {
    int i = blockIdx.x * 256 + threadIdx.x;
    if (i < N_ROWS) g_ncand[i] = 0;
    if (i < K_CENT) g_counts[i] = 0;
}

// ---------------- kernel: mma.sync bf16 GEMM  sim = A @ B^T ------------------
// tile 128(M) x 256(N), BK=32, 3-stage cp.async pipeline; M-chunked for overlap
#define GBM 128
#define GBN 256
#define GSTAGE_BYTES 30720        // A 128x80B=10240 + B 256x80B=20480
#define GSM_TOTAL (3 * GSTAGE_BYTES)   // 92160
#define NKSTEP 16                 // 512 / 32

__device__ __forceinline__ void g_load_stage(uint32_t smemU, int st, int kstep,
                                             int m0, int n0, int tid) {
    const int kin = kstep * 32;
    const uint32_t sA = smemU + st * GSTAGE_BYTES;
    const uint32_t sB = sA + 10240;
#pragma unroll
    for (int h = 0; h < 6; h++) {
        const int c = tid + h * 256;            // 0..1535
        if (c < 512) {
            const int row = c >> 2, q = c & 3;
            const void* src = g_Abf + (size_t)(m0 + row) * D_DIM + kin + q * 8;
            const uint32_t dst = sA + row * 80 + q * 16;
            asm volatile("cp.async.cg.shared.global [%0], [%1], 16;" :: "r"(dst), "l"(src));
        } else {
            const int c2 = c - 512;
            const int row = c2 >> 2, q = c2 & 3;
            const void* src = g_Bbf + (size_t)(n0 + row) * D_DIM + kin + q * 8;
            const uint32_t dst = sB + row * 80 + q * 16;
            asm volatile("cp.async.cg.shared.global [%0], [%1], 16;" :: "r"(dst), "l"(src));
        }
    }
}

__global__ __launch_bounds__(256, 1)
void vq_gemm_mma(int mbase) {
    extern __shared__ char gsm[];
    const uint32_t smemU = smem_u32(gsm);
    const int tid = threadIdx.x;
    const int lane = tid & 31;
    const int w = tid >> 5;
    const int wm = (w & 1) * 64;       // warp m-offset (2 warps in M)
    const int wn = (w >> 1) * 64;      // warp n-offset (4 warps in N)
    const int n0 = blockIdx.x * GBN;
    const int m0 = mbase + blockIdx.y * GBM;

    float acc[4][8][4];
#pragma unroll
    for (int a = 0; a < 4; a++)
#pragma unroll
        for (int b = 0; b < 8; b++)
#pragma unroll
            for (int c = 0; c < 4; c++) acc[a][b][c] = 0.f;

    g_load_stage(smemU, 0, 0, m0, n0, tid);
    asm volatile("cp.async.commit_group;" ::: "memory");
    g_load_stage(smemU, 1, 1, m0, n0, tid);
    asm volatile("cp.async.commit_group;" ::: "memory");

    int st = 0, ls = 2;
    for (int i = 0; i < NKSTEP; i++) {
        if (i + 2 < NKSTEP) asm volatile("cp.async.wait_group 1;" ::: "memory");
        else                asm volatile("cp.async.wait_group 0;" ::: "memory");
        __syncthreads();
        if (i + 2 < NKSTEP) {
            g_load_stage(smemU, ls, i + 2, m0, n0, tid);
            asm volatile("cp.async.commit_group;" ::: "memory");
            ls = (ls == 2) ? 0 : ls + 1;
        }
        const uint32_t sA = smemU + st * GSTAGE_BYTES;
        const uint32_t sB = sA + 10240;
#pragma unroll
        for (int k16 = 0; k16 < 32; k16 += 16) {
            uint32_t a[4][4], b[4][4];
#pragma unroll
            for (int mt = 0; mt < 4; mt++) {
                const uint32_t addr = sA + (wm + mt * 16 + (lane & 15)) * 80
                                         + (k16 + ((lane >> 4) << 3)) * 2;
                asm volatile("ldmatrix.sync.aligned.m8n8.x4.shared.b16 {%0,%1,%2,%3}, [%4];"
                    : "=r"(a[mt][0]), "=r"(a[mt][1]), "=r"(a[mt][2]), "=r"(a[mt][3])
                    : "r"(addr));
            }
#pragma unroll
            for (int nt2 = 0; nt2 < 4; nt2++) {
                const uint32_t addr = sB + (wn + nt2 * 16 + ((lane >> 4) & 1) * 8 + (lane & 7)) * 80
                                         + (k16 + ((lane >> 3) & 1) * 8) * 2;
                asm volatile("ldmatrix.sync.aligned.m8n8.x4.shared.b16 {%0,%1,%2,%3}, [%4];"
                    : "=r"(b[nt2][0]), "=r"(b[nt2][1]), "=r"(b[nt2][2]), "=r"(b[nt2][3])
                    : "r"(addr));
            }
#pragma unroll
            for (int mt = 0; mt < 4; mt++)
#pragma unroll
                for (int nt = 0; nt < 8; nt++) {
                    asm volatile(
                        "mma.sync.aligned.m16n8k16.row.col.f32.bf16.bf16.f32 "
                        "{%0,%1,%2,%3},{%4,%5,%6,%7},{%8,%9},{%0,%1,%2,%3};"
                        : "+f"(acc[mt][nt][0]), "+f"(acc[mt][nt][1]),
                          "+f"(acc[mt][nt][2]), "+f"(acc[mt][nt][3])
                        : "r"(a[mt][0]), "r"(a[mt][1]), "r"(a[mt][2]), "r"(a[mt][3]),
                          "r"(b[nt >> 1][(nt & 1) * 2]), "r"(b[nt >> 1][(nt & 1) * 2 + 1]));
                }
        }
        st = (st == 2) ? 0 : st + 1;
    }

    // epilogue: bf16 stores
#pragma unroll
    for (int mt = 0; mt < 4; mt++) {
        const int r0 = m0 + wm + mt * 16 + (lane >> 2);
        const int cb = n0 + wn + (lane & 3) * 2;
#pragma unroll
        for (int nt = 0; nt < 8; nt++) {
            __nv_bfloat16* p0 = g_simh + (size_t)r0 * K_CENT + cb + nt * 8;
            __nv_bfloat16* p1 = p0 + (size_t)8 * K_CENT;
            *(__nv_bfloat162*)p0 = __floats2bfloat162_rn(acc[mt][nt][0], acc[mt][nt][1]);
            *(__nv_bfloat162*)p1 = __floats2bfloat162_rn(acc[mt][nt][2], acc[mt][nt][3]);
        }
    }
}

// ---------------- kernel: softmax / candidates / entropy / diversity ---------
// thread t owns columns [8t, 8t+8) of every row; diversity partials in registers
__global__ __launch_bounds__(256)
void vq_softmax(int blkbase) {
    __shared__ float warr[8], wS[8], wT[8];
    const int t = threadIdx.x;
    const int lane = t & 31;
    const int w = t >> 5;
    const int gblk = blkbase + blockIdx.x;
    const int row0 = gblk * ROWS_PER_BLK;

    float pdiv[8];
#pragma unroll
    for (int j = 0; j < 8; j++) pdiv[j] = 0.f;
    float hacc = 0.f;

    for (int r = 0; r < ROWS_PER_BLK; ++r) {
        const int n = row0 + r;
        const uint4 raw = ((const uint4*)g_simh)[(size_t)n * (K_CENT / 8) + t];
        float v[8];
        {
            const __nv_bfloat162* h2 = (const __nv_bfloat162*)&raw;
#pragma unroll
            for (int p = 0; p < 4; p++) {
                float2 f = __bfloat1622float2(h2[p]);
                v[p * 2] = f.x; v[p * 2 + 1] = f.y;
            }
        }

        float mv = v[0];
#pragma unroll
        for (int j = 1; j < 8; j++) mv = fmaxf(mv, v[j]);
#pragma unroll
        for (int o = 16; o > 0; o >>= 1) mv = fmaxf(mv, __shfl_xor_sync(0xffffffffu, mv, o));
        if (lane == 0) warr[w] = mv;
        __syncthreads();
        float rowmax = warr[0];
#pragma unroll
        for (int k = 1; k < 8; k++) rowmax = fmaxf(rowmax, warr[k]);

        // candidates within DELTA of approx max -> global list (order-independent winner)
#pragma unroll
        for (int j = 0; j < 8; j++) {
            if (v[j] >= rowmax - DELTA) {
                int s = atomicAdd(&g_ncand[n], 1);
                if (s < 32) g_cand[(size_t)n * 32 + s] = t * 8 + j;
            }
        }

        float e[8], ls = 0.f, ts = 0.f;
#pragma unroll
        for (int j = 0; j < 8; j++) {
            float u = v[j] - rowmax;
            float ee = __expf(u);
            e[j] = ee; ls += ee; ts += ee * u;
        }
#pragma unroll
        for (int o = 16; o > 0; o >>= 1) {
            ls += __shfl_xor_sync(0xffffffffu, ls, o);
            ts += __shfl_xor_sync(0xffffffffu, ts, o);
        }
        if (lane == 0) { wS[w] = ls; wT[w] = ts; }
        __syncthreads();
        float S = 0.f, T = 0.f;
#pragma unroll
        for (int k = 0; k < 8; k++) { S += wS[k]; T += wT[k]; }
        const float invS = 1.0f / S;

#pragma unroll
        for (int j = 0; j < 8; j++) pdiv[j] += e[j] * invS;
        // sum_k p*log2(p) = log2e*(T/S) - log2(S)
        if (t == 0) hacc += 1.44269504f * (T * invS) - __log2f(S);
    }

    float* dp = g_div_part + (size_t)gblk * K_CENT + t * 8;
    *(float4*)(dp)     = make_float4(pdiv[0], pdiv[1], pdiv[2], pdiv[3]);
    *(float4*)(dp + 4) = make_float4(pdiv[4], pdiv[5], pdiv[6], pdiv[7]);
    if (t == 0) g_h_part[gblk] = hacc;
}

// ---------------- kernel: exact argmax refine + counts + quantize (fused) ----
// one warp per row
__global__ __launch_bounds__(256)
void vq_refine(const float* __restrict__ inputs, const float* __restrict__ codebook,
               float* __restrict__ out_idx, float* __restrict__ out_q) {
    const int t = threadIdx.x;
    const int lane = t & 31;
    const int w = t >> 5;
    const int n = blockIdx.x * 8 + w;

    const int nc = min(g_ncand[n], 32);
    float bestv = -3.4e38f; int besti = 0x7fffffff;
    const float4* ar = (const float4*)(inputs + (size_t)n * D_DIM);
    for (int c = 0; c < nc; ++c) {
        const int k = g_cand[(size_t)n * 32 + c];
        const float4* br = (const float4*)(codebook + (size_t)k * D_DIM);
        float part = 0.f;
#pragma unroll 4
        for (int i = lane; i < D_DIM / 4; i += 32) {
            float4 a = ar[i], b = br[i];
            part += a.x * b.x + a.y * b.y + a.z * b.z + a.w * b.w;
        }
#pragma unroll
        for (int o = 16; o > 0; o >>= 1)
            part += __shfl_xor_sync(0xffffffffu, part, o);
        if (part > bestv || (part == bestv && k < besti)) { bestv = part; besti = k; }
    }
    if (lane == 0) {
        out_idx[n] = (float)besti;
        atomicAdd(&g_counts[besti], 1);
    }

    // fused quantize: center, normalize, STE
    const float4* br = (const float4*)(codebook + (size_t)besti * D_DIM);
    float4 q[4];
    float s = 0.f;
#pragma unroll
    for (int i = 0; i < 4; i++) {
        q[i] = br[lane + 32 * i];
        s += q[i].x + q[i].y + q[i].z + q[i].w;
    }
#pragma unroll
    for (int o = 16; o > 0; o >>= 1) s += __shfl_xor_sync(0xffffffffu, s, o);
    const float mean = s * (1.0f / (float)D_DIM);

    float ss = 0.f;
#pragma unroll
    for (int i = 0; i < 4; i++) {
        q[i].x -= mean; q[i].y -= mean; q[i].z -= mean; q[i].w -= mean;
        ss += q[i].x * q[i].x + q[i].y * q[i].y + q[i].z * q[i].z + q[i].w * q[i].w;
    }
#pragma unroll
    for (int o = 16; o > 0; o >>= 1) ss += __shfl_xor_sync(0xffffffffu, ss, o);
    const float inv = 1.0f / sqrtf(ss);

    float4* oq = (float4*)(out_q + (size_t)n * D_DIM);
#pragma unroll
    for (int i = 0; i < 4; i++) {
        const float4 x = ar[lane + 32 * i];
        float4 o;
        o.x = x.x + (q[i].x * inv - x.x);
        o.y = x.y + (q[i].y * inv - x.y);
        o.z = x.z + (q[i].z * inv - x.z);
        o.w = x.w + (q[i].w * inv - x.w);
        oq[lane + 32 * i] = o;
    }
}

// ---------------- kernel: deterministic diversity reduction ------------------
__global__ __launch_bounds__(256)
void vq_div_reduce() {
    const int k = blockIdx.x * 256 + threadIdx.x;  // 0..2047 (gridDim.x = 8)
    const int chunk = blockIdx.y;                  // 0..15
    const int b0 = chunk * 64;
    float s0 = 0.f, s1 = 0.f, s2 = 0.f, s3 = 0.f;
    for (int b = 0; b < 64; b += 4) {
        s0 += g_div_part[(size_t)(b0 + b + 0) * K_CENT + k];
        s1 += g_div_part[(size_t)(b0 + b + 1) * K_CENT + k];
        s2 += g_div_part[(size_t)(b0 + b + 2) * K_CENT + k];
        s3 += g_div_part[(size_t)(b0 + b + 3) * K_CENT + k];
    }
    g_div2[chunk * K_CENT + k] = (s0 + s1) + (s2 + s3);
}

// ---------------- kernel: finalize loss + EMA counts -------------------------
__global__ __launch_bounds__(256)
void vq_finalize(const float* __restrict__ cluster_counts,
                 const int* __restrict__ train,
                 float* __restrict__ out_counts) {
    __shared__ float redf[256];
    const int t = threadIdx.x;
    const int tr = train[0];

    float hdiv = 0.f;
    for (int k = t; k < K_CENT; k += 256) {
        float s = 0.f;
#pragma unroll
        for (int ch = 0; ch < 16; ch++) s += g_div2[ch * K_CENT + k];
        float d = s * (1.0f / (float)N_ROWS);
        hdiv += d * __log2f(d + EPSF);
        float cnt = (float)g_counts[k];
        float oc  = cluster_counts[k];
        out_counts[k] = tr ? (EMA * oc + (1.0f - EMA) * cnt) : oc;
    }
    float hsum = 0.f;
    for (int i = t; i < NBLK_SM; i += 256) hsum += g_h_part[i];

    redf[t] = hdiv;
    __syncthreads();
    for (int s = 128; s > 0; s >>= 1) { if (t < s) redf[t] += redf[t + s]; __syncthreads(); }
    const float hdiv_tot = redf[0];
    __syncthreads();
    redf[t] = hsum;
    __syncthreads();
    for (int s = 128; s > 0; s >>= 1) { if (t < s) redf[t] += redf[t + s]; __syncthreads(); }
    if (t == 0) {
        float h_clust     = -(redf[0] / (float)N_ROWS);
        float h_diversity = -hdiv_tot;
        g_loss = h_clust - GAMMAF * h_diversity;
    }
}

// ---------------- kernel: broadcast-fill quantization_loss -------------------
__global__ __launch_bounds__(256)
void vq_fill(float* __restrict__ dst) {
    const float v = g_loss;
    const float4 f = make_float4(v, v, v, v);
    size_t i = (size_t)blockIdx.x * 256 + threadIdx.x;
#pragma unroll
    for (int j = 0; j < 4; j++)
        __stcs(((float4*)dst) + i + (size_t)j * 2097152, f);
}

// ---------------- launcher ---------------------------------------------------
extern "C" void kernel_launch(void* const* d_in, const int* in_sizes, int n_in,
                              void* d_out, int out_size) {
    const float* inputs   = (const float*)d_in[0];
    const float* codebook = (const float*)d_in[1];
    const float* ccounts  = (const float*)d_in[2];
    const int*   train    = (const int*)d_in[3];
    float* out = (float*)d_out;

    static bool inited = false;
    static cudaStream_t s1, s2;
    static cudaEvent_t evStart, evG[NCHUNK], evSall, evR, evCb;
    if (!inited) {
        cudaFuncSetAttribute(vq_gemm_mma, cudaFuncAttributeMaxDynamicSharedMemorySize, GSM_TOTAL);
        cudaStreamCreateWithFlags(&s1, cudaStreamNonBlocking);
        cudaStreamCreateWithFlags(&s2, cudaStreamNonBlocking);
        cudaEventCreateWithFlags(&evStart, cudaEventDisableTiming);
        for (int c = 0; c < NCHUNK; c++) cudaEventCreateWithFlags(&evG[c], cudaEventDisableTiming);
        cudaEventCreateWithFlags(&evSall, cudaEventDisableTiming);
        cudaEventCreateWithFlags(&evR, cudaEventDisableTiming);
        cudaEventCreateWithFlags(&evCb, cudaEventDisableTiming);
        inited = true;
    }

    // stream 0: convert + init, then GEMM in M-chunks
    vq_convert<<<9216, 256>>>(inputs, codebook);
    vq_init<<<64, 256>>>();
    cudaEventRecord(evStart, 0);

    // s2: codebook copy overlapped with GEMM
    cudaStreamWaitEvent(s2, evStart, 0);
    cudaMemcpyAsync(out + OFF_CB, d_in[1], (size_t)K_CENT * D_DIM * sizeof(float),
                    cudaMemcpyDeviceToDevice, s2);
    cudaEventRecord(evCb, s2);

    for (int c = 0; c < NCHUNK; c++) {
        vq_gemm_mma<<<dim3(K_CENT / GBN, MTILE_PER_CHUNK), 256, GSM_TOTAL>>>(
            c * MTILE_PER_CHUNK * GBM);
        cudaEventRecord(evG[c], 0);
        // s1: softmax chunk c as soon as its rows are ready
        cudaStreamWaitEvent(s1, evG[c], 0);
        vq_softmax<<<BLK_PER_CHUNK, 256, 0, s1>>>(c * BLK_PER_CHUNK);
    }
    cudaEventRecord(evSall, s1);

    // s2: refine (argmax + quantize) overlapped with loss chain
    cudaStreamWaitEvent(s2, evSall, 0);
    vq_refine<<<N_ROWS / 8, 256, 0, s2>>>(inputs, codebook, out + OFF_IDX, out + OFF_Q);
    cudaEventRecord(evR, s2);

    // stream 0: loss chain after all softmax chunks
    cudaStreamWaitEvent(0, evSall, 0);
    vq_div_reduce<<<dim3(8, 16), 256>>>();
    // finalize needs g_counts from refine
    cudaStreamWaitEvent(0, evR, 0);
    vq_finalize<<<1, 256>>>(ccounts, train, out + OFF_CNT);
    vq_fill<<<8192, 256>>>(out + OFF_LOSS);

    // join remaining forked work back to stream 0
    cudaStreamWaitEvent(0, evCb, 0);
    (void)in_sizes; (void)n_in; (void)out_size;
}

// round 10
// speedup vs baseline: 1.1367x; 1.1367x over previous
#include <cuda_runtime.h>
#include <cuda_bf16.h>
#include <cstdint>
#include <cstddef>

// Problem constants
#define N_ROWS   16384
#define D_DIM    512
#define K_CENT   2048
#define EMA      0.99f
#define GAMMAF   1.0f
#define EPSF     1e-8f
#define DELTA    6e-2f
#define ROWS_PER_BLK 16
#define NBLK_SM  (N_ROWS / ROWS_PER_BLK)   // 1024

// Output layout (float32, concatenated in reference return order)
#define OFF_Q    ((size_t)0)
#define OFF_LOSS ((size_t)8388608)
#define OFF_IDX  ((size_t)41943040)
#define OFF_CB   ((size_t)41959424)
#define OFF_CNT  ((size_t)43008000)

// ---------------- scratch (static device memory) -----------------------------
__device__ __align__(16) __nv_bfloat16 g_simh[(size_t)N_ROWS * K_CENT];   // 67 MB
__device__ float g_div_part[(size_t)NBLK_SM * K_CENT];    // 8 MB
__device__ float g_div2[16 * K_CENT];
__device__ float g_h_part[NBLK_SM];
__device__ int   g_counts[K_CENT];
__device__ float g_loss;
__device__ int   g_cand[(size_t)N_ROWS * 32];             // 2 MB
__device__ int   g_ncand[N_ROWS];
__device__ __align__(16) int8_t g_Aq[(size_t)N_ROWS * D_DIM];  // 8.4 MB
__device__ __align__(16) int8_t g_Bq[(size_t)K_CENT * D_DIM];  // 1 MB
__device__ float g_sA[N_ROWS];
__device__ float g_sB[K_CENT];

__device__ __forceinline__ uint32_t smem_u32(const void* p) {
    uint32_t a;
    asm("{ .reg .u64 t; cvta.to.shared.u64 t, %1; cvt.u32.u64 %0, t; }" : "=r"(a) : "l"(p));
    return a;
}

// ---------------- kernel: per-row int8 quantization (A and B) ----------------
// one warp per row; lane handles 16 consecutive elements
__global__ __launch_bounds__(256)
void vq_quant(const float* __restrict__ A, const float* __restrict__ B) {
    const int gw = blockIdx.x * 8 + (threadIdx.x >> 5);
    const int lane = threadIdx.x & 31;
    const float* src; int8_t* dst; float* sout;
    if (gw < N_ROWS) {
        src = A + (size_t)gw * D_DIM; dst = g_Aq + (size_t)gw * D_DIM; sout = &g_sA[gw];
    } else {
        const int r = gw - N_ROWS;
        if (r >= K_CENT) return;
        src = B + (size_t)r * D_DIM; dst = g_Bq + (size_t)r * D_DIM; sout = &g_sB[r];
    }
    float4 x[4];
    float m = 0.f;
#pragma unroll
    for (int i = 0; i < 4; i++) {
        x[i] = ((const float4*)src)[lane * 4 + i];
        m = fmaxf(m, fmaxf(fmaxf(fabsf(x[i].x), fabsf(x[i].y)),
                           fmaxf(fabsf(x[i].z), fabsf(x[i].w))));
    }
#pragma unroll
    for (int o = 16; o > 0; o >>= 1) m = fmaxf(m, __shfl_xor_sync(0xffffffffu, m, o));
    const float inv = (m > 0.f) ? (127.0f / m) : 0.f;
    uint32_t p[4];
#pragma unroll
    for (int i = 0; i < 4; i++) {
        int a0 = __float2int_rn(x[i].x * inv);
        int a1 = __float2int_rn(x[i].y * inv);
        int a2 = __float2int_rn(x[i].z * inv);
        int a3 = __float2int_rn(x[i].w * inv);
        p[i] = (a0 & 0xff) | ((a1 & 0xff) << 8) | ((a2 & 0xff) << 16) | ((a3 & 0xff) << 24);
    }
    ((uint4*)dst)[lane] = make_uint4(p[0], p[1], p[2], p[3]);
    if (lane == 0) *sout = m * (1.0f / 127.0f);
}

// ---------------- kernel: reset counters --------------------------------------
__global__ __launch_bounds__(256)
void vq_init() {
    int i = blockIdx.x * 256 + threadIdx.x;
    if (i < N_ROWS) g_ncand[i] = 0;
    if (i < K_CENT) g_counts[i] = 0;
}

// ---------------- kernel: mma.sync s8 GEMM  sim = (sA.sB) * (Aq @ Bq^T) ------
// tile 128(M) x 256(N), BK=64 int8 (64B/row, same bytes as bf16 BK=32)
#define GBM 128
#define GBN 256
#define GSTAGE_BYTES 30720        // A 128x80B + B 256x80B
#define GSM_TOTAL (3 * GSTAGE_BYTES)   // 92160
#define NKSTEP 8                  // 512 / 64

__device__ __forceinline__ void g_load_stage(uint32_t smemU, int st, int kstep,
                                             int m0, int n0, int tid) {
    const int kin = kstep * 64;       // byte offset in row
    const uint32_t sA = smemU + st * GSTAGE_BYTES;
    const uint32_t sB = sA + 10240;
#pragma unroll
    for (int h = 0; h < 6; h++) {
        const int c = tid + h * 256;            // 0..1535
        if (c < 512) {
            const int row = c >> 2, q = c & 3;
            const void* src = g_Aq + (size_t)(m0 + row) * D_DIM + kin + q * 16;
            const uint32_t dst = sA + row * 80 + q * 16;
            asm volatile("cp.async.cg.shared.global [%0], [%1], 16;" :: "r"(dst), "l"(src));
        } else {
            const int c2 = c - 512;
            const int row = c2 >> 2, q = c2 & 3;
            const void* src = g_Bq + (size_t)(n0 + row) * D_DIM + kin + q * 16;
            const uint32_t dst = sB + row * 80 + q * 16;
            asm volatile("cp.async.cg.shared.global [%0], [%1], 16;" :: "r"(dst), "l"(src));
        }
    }
}

__global__ __launch_bounds__(256, 1)
void vq_gemm_mma() {
    extern __shared__ char gsm[];
    const uint32_t smemU = smem_u32(gsm);
    const int tid = threadIdx.x;
    const int lane = tid & 31;
    const int w = tid >> 5;
    const int wm = (w & 1) * 64;       // warp m-offset (2 warps in M)
    const int wn = (w >> 1) * 64;      // warp n-offset (4 warps in N)
    const int n0 = blockIdx.x * GBN;
    const int m0 = blockIdx.y * GBM;

    int acc[4][8][4];
#pragma unroll
    for (int a = 0; a < 4; a++)
#pragma unroll
        for (int b = 0; b < 8; b++)
#pragma unroll
            for (int c = 0; c < 4; c++) acc[a][b][c] = 0;

    g_load_stage(smemU, 0, 0, m0, n0, tid);
    asm volatile("cp.async.commit_group;" ::: "memory");
    g_load_stage(smemU, 1, 1, m0, n0, tid);
    asm volatile("cp.async.commit_group;" ::: "memory");

    int st = 0, ls = 2;
    for (int i = 0; i < NKSTEP; i++) {
        if (i + 2 < NKSTEP) asm volatile("cp.async.wait_group 1;" ::: "memory");
        else                asm volatile("cp.async.wait_group 0;" ::: "memory");
        __syncthreads();
        if (i + 2 < NKSTEP) {
            g_load_stage(smemU, ls, i + 2, m0, n0, tid);
            asm volatile("cp.async.commit_group;" ::: "memory");
            ls = (ls == 2) ? 0 : ls + 1;
        }
        const uint32_t sA = smemU + st * GSTAGE_BYTES;
        const uint32_t sB = sA + 10240;
#pragma unroll
        for (int k16 = 0; k16 < 32; k16 += 16) {   // two 32-byte k-substeps
            uint32_t a[4][4], b[4][4];
#pragma unroll
            for (int mt = 0; mt < 4; mt++) {
                const uint32_t addr = sA + (wm + mt * 16 + (lane & 15)) * 80
                                         + (k16 + ((lane >> 4) << 3)) * 2;
                asm volatile("ldmatrix.sync.aligned.m8n8.x4.shared.b16 {%0,%1,%2,%3}, [%4];"
                    : "=r"(a[mt][0]), "=r"(a[mt][1]), "=r"(a[mt][2]), "=r"(a[mt][3])
                    : "r"(addr));
            }
#pragma unroll
            for (int nt2 = 0; nt2 < 4; nt2++) {
                const uint32_t addr = sB + (wn + nt2 * 16 + ((lane >> 4) & 1) * 8 + (lane & 7)) * 80
                                         + (k16 + ((lane >> 3) & 1) * 8) * 2;
                asm volatile("ldmatrix.sync.aligned.m8n8.x4.shared.b16 {%0,%1,%2,%3}, [%4];"
                    : "=r"(b[nt2][0]), "=r"(b[nt2][1]), "=r"(b[nt2][2]), "=r"(b[nt2][3])
                    : "r"(addr));
            }
#pragma unroll
            for (int mt = 0; mt < 4; mt++)
#pragma unroll
                for (int nt = 0; nt < 8; nt++) {
                    asm volatile(
                        "mma.sync.aligned.m16n8k32.row.col.s32.s8.s8.s32 "
                        "{%0,%1,%2,%3},{%4,%5,%6,%7},{%8,%9},{%0,%1,%2,%3};"
                        : "+r"(acc[mt][nt][0]), "+r"(acc[mt][nt][1]),
                          "+r"(acc[mt][nt][2]), "+r"(acc[mt][nt][3])
                        : "r"(a[mt][0]), "r"(a[mt][1]), "r"(a[mt][2]), "r"(a[mt][3]),
                          "r"(b[nt >> 1][(nt & 1) * 2]), "r"(b[nt >> 1][(nt & 1) * 2 + 1]));
                }
        }
        st = (st == 2) ? 0 : st + 1;
    }

    // epilogue: apply per-row scales, store bf16
    float sbv[8][2];
#pragma unroll
    for (int nt = 0; nt < 8; nt++) {
        const int cb = n0 + wn + (lane & 3) * 2 + nt * 8;
        sbv[nt][0] = g_sB[cb];
        sbv[nt][1] = g_sB[cb + 1];
    }
#pragma unroll
    for (int mt = 0; mt < 4; mt++) {
        const int r0 = m0 + wm + mt * 16 + (lane >> 2);
        const float sa0 = g_sA[r0];
        const float sa1 = g_sA[r0 + 8];
        const int cb = n0 + wn + (lane & 3) * 2;
#pragma unroll
        for (int nt = 0; nt < 8; nt++) {
            __nv_bfloat16* p0 = g_simh + (size_t)r0 * K_CENT + cb + nt * 8;
            __nv_bfloat16* p1 = p0 + (size_t)8 * K_CENT;
            *(__nv_bfloat162*)p0 = __floats2bfloat162_rn(sa0 * sbv[nt][0] * (float)acc[mt][nt][0],
                                                         sa0 * sbv[nt][1] * (float)acc[mt][nt][1]);
            *(__nv_bfloat162*)p1 = __floats2bfloat162_rn(sa1 * sbv[nt][0] * (float)acc[mt][nt][2],
                                                         sa1 * sbv[nt][1] * (float)acc[mt][nt][3]);
        }
    }
}

// ---------------- kernel: softmax / candidates / entropy / diversity ---------
__global__ __launch_bounds__(256)
void vq_softmax() {
    __shared__ float warr[8], wS[8], wT[8];
    const int t = threadIdx.x;
    const int lane = t & 31;
    const int w = t >> 5;
    const int row0 = blockIdx.x * ROWS_PER_BLK;

    float pdiv[8];
#pragma unroll
    for (int j = 0; j < 8; j++) pdiv[j] = 0.f;
    float hacc = 0.f;

    for (int r = 0; r < ROWS_PER_BLK; ++r) {
        const int n = row0 + r;
        const uint4 raw = ((const uint4*)g_simh)[(size_t)n * (K_CENT / 8) + t];
        float v[8];
        {
            const __nv_bfloat162* h2 = (const __nv_bfloat162*)&raw;
#pragma unroll
            for (int p = 0; p < 4; p++) {
                float2 f = __bfloat1622float2(h2[p]);
                v[p * 2] = f.x; v[p * 2 + 1] = f.y;
            }
        }

        float mv = v[0];
#pragma unroll
        for (int j = 1; j < 8; j++) mv = fmaxf(mv, v[j]);
#pragma unroll
        for (int o = 16; o > 0; o >>= 1) mv = fmaxf(mv, __shfl_xor_sync(0xffffffffu, mv, o));
        if (lane == 0) warr[w] = mv;
        __syncthreads();
        float rowmax = warr[0];
#pragma unroll
        for (int k = 1; k < 8; k++) rowmax = fmaxf(rowmax, warr[k]);

        // candidates within DELTA of approx max -> global list (order-independent winner)
#pragma unroll
        for (int j = 0; j < 8; j++) {
            if (v[j] >= rowmax - DELTA) {
                int s = atomicAdd(&g_ncand[n], 1);
                if (s < 32) g_cand[(size_t)n * 32 + s] = t * 8 + j;
            }
        }

        float e[8], ls = 0.f, ts = 0.f;
#pragma unroll
        for (int j = 0; j < 8; j++) {
            float u = v[j] - rowmax;
            float ee = __expf(u);
            e[j] = ee; ls += ee; ts += ee * u;
        }
#pragma unroll
        for (int o = 16; o > 0; o >>= 1) {
            ls += __shfl_xor_sync(0xffffffffu, ls, o);
            ts += __shfl_xor_sync(0xffffffffu, ts, o);
        }
        if (lane == 0) { wS[w] = ls; wT[w] = ts; }
        __syncthreads();
        float S = 0.f, T = 0.f;
#pragma unroll
        for (int k = 0; k < 8; k++) { S += wS[k]; T += wT[k]; }
        const float invS = 1.0f / S;

#pragma unroll
        for (int j = 0; j < 8; j++) pdiv[j] += e[j] * invS;
        // sum_k p*log2(p) = log2e*(T/S) - log2(S)
        if (t == 0) hacc += 1.44269504f * (T * invS) - __log2f(S);
    }

    float* dp = g_div_part + (size_t)blockIdx.x * K_CENT + t * 8;
    *(float4*)(dp)     = make_float4(pdiv[0], pdiv[1], pdiv[2], pdiv[3]);
    *(float4*)(dp + 4) = make_float4(pdiv[4], pdiv[5], pdiv[6], pdiv[7]);
    if (t == 0) g_h_part[blockIdx.x] = hacc;
}

// ---------------- kernel: exact argmax refine + counts + quantize (fused) ----
// one warp per row; decision numerics frozen (exact fp32 dot, (max, min-idx))
__global__ __launch_bounds__(256)
void vq_refine(const float* __restrict__ inputs, const float* __restrict__ codebook,
               float* __restrict__ out_idx, float* __restrict__ out_q) {
    const int t = threadIdx.x;
    const int lane = t & 31;
    const int w = t >> 5;
    const int n = blockIdx.x * 8 + w;

    const int nc = min(g_ncand[n], 32);
    float bestv = -3.4e38f; int besti = 0x7fffffff;
    const float4* ar = (const float4*)(inputs + (size_t)n * D_DIM);
    for (int c = 0; c < nc; ++c) {
        const int k = g_cand[(size_t)n * 32 + c];
        const float4* br = (const float4*)(codebook + (size_t)k * D_DIM);
        float part = 0.f;
#pragma unroll 4
        for (int i = lane; i < D_DIM / 4; i += 32) {
            float4 a = ar[i], b = br[i];
            part += a.x * b.x + a.y * b.y + a.z * b.z + a.w * b.w;
        }
#pragma unroll
        for (int o = 16; o > 0; o >>= 1)
            part += __shfl_xor_sync(0xffffffffu, part, o);
        if (part > bestv || (part == bestv && k < besti)) { bestv = part; besti = k; }
    }
    if (lane == 0) {
        out_idx[n] = (float)besti;
        atomicAdd(&g_counts[besti], 1);
    }

    // fused quantize: center, normalize, STE
    const float4* br = (const float4*)(codebook + (size_t)besti * D_DIM);
    float4 q[4];
    float s = 0.f;
#pragma unroll
    for (int i = 0; i < 4; i++) {
        q[i] = br[lane + 32 * i];
        s += q[i].x + q[i].y + q[i].z + q[i].w;
    }
#pragma unroll
    for (int o = 16; o > 0; o >>= 1) s += __shfl_xor_sync(0xffffffffu, s, o);
    const float mean = s * (1.0f / (float)D_DIM);

    float ss = 0.f;
#pragma unroll
    for (int i = 0; i < 4; i++) {
        q[i].x -= mean; q[i].y -= mean; q[i].z -= mean; q[i].w -= mean;
        ss += q[i].x * q[i].x + q[i].y * q[i].y + q[i].z * q[i].z + q[i].w * q[i].w;
    }
#pragma unroll
    for (int o = 16; o > 0; o >>= 1) ss += __shfl_xor_sync(0xffffffffu, ss, o);
    const float inv = 1.0f / sqrtf(ss);

    float4* oq = (float4*)(out_q + (size_t)n * D_DIM);
#pragma unroll
    for (int i = 0; i < 4; i++) {
        const float4 x = ar[lane + 32 * i];
        float4 o;
        o.x = x.x + (q[i].x * inv - x.x);
        o.y = x.y + (q[i].y * inv - x.y);
        o.z = x.z + (q[i].z * inv - x.z);
        o.w = x.w + (q[i].w * inv - x.w);
        oq[lane + 32 * i] = o;
    }
}

// ---------------- kernel: deterministic diversity reduction ------------------
__global__ __launch_bounds__(256)
void vq_div_reduce() {
    const int k = blockIdx.x * 256 + threadIdx.x;  // 0..2047 (gridDim.x = 8)
    const int chunk = blockIdx.y;                  // 0..15
    const int b0 = chunk * 64;
    float s0 = 0.f, s1 = 0.f, s2 = 0.f, s3 = 0.f;
    for (int b = 0; b < 64; b += 4) {
        s0 += g_div_part[(size_t)(b0 + b + 0) * K_CENT + k];
        s1 += g_div_part[(size_t)(b0 + b + 1) * K_CENT + k];
        s2 += g_div_part[(size_t)(b0 + b + 2) * K_CENT + k];
        s3 += g_div_part[(size_t)(b0 + b + 3) * K_CENT + k];
    }
    g_div2[chunk * K_CENT + k] = (s0 + s1) + (s2 + s3);
}

// ---------------- kernel: finalize loss + EMA counts -------------------------
__global__ __launch_bounds__(256)
void vq_finalize(const float* __restrict__ cluster_counts,
                 const int* __restrict__ train,
                 float* __restrict__ out_counts) {
    __shared__ float redf[256];
    const int t = threadIdx.x;
    const int tr = train[0];

    float hdiv = 0.f;
    for (int k = t; k < K_CENT; k += 256) {
        float s = 0.f;
#pragma unroll
        for (int ch = 0; ch < 16; ch++) s += g_div2[ch * K_CENT + k];
        float d = s * (1.0f / (float)N_ROWS);
        hdiv += d * __log2f(d + EPSF);
        float cnt = (float)g_counts[k];
        float oc  = cluster_counts[k];
        out_counts[k] = tr ? (EMA * oc + (1.0f - EMA) * cnt) : oc;
    }
    float hsum = 0.f;
    for (int i = t; i < NBLK_SM; i += 256) hsum += g_h_part[i];

    redf[t] = hdiv;
    __syncthreads();
    for (int s = 128; s > 0; s >>= 1) { if (t < s) redf[t] += redf[t + s]; __syncthreads(); }
    const float hdiv_tot = redf[0];
    __syncthreads();
    redf[t] = hsum;
    __syncthreads();
    for (int s = 128; s > 0; s >>= 1) { if (t < s) redf[t] += redf[t + s]; __syncthreads(); }
    if (t == 0) {
        float h_clust     = -(redf[0] / (float)N_ROWS);
        float h_diversity = -hdiv_tot;
        g_loss = h_clust - GAMMAF * h_diversity;
    }
}

// ---------------- kernel: broadcast-fill quantization_loss -------------------
__global__ __launch_bounds__(256)
void vq_fill(float* __restrict__ dst) {
    const float v = g_loss;
    const float4 f = make_float4(v, v, v, v);
    size_t i = (size_t)blockIdx.x * 256 + threadIdx.x;
#pragma unroll
    for (int j = 0; j < 4; j++)
        __stcs(((float4*)dst) + i + (size_t)j * 2097152, f);
}

// ---------------- launcher (single stream, R7 structure) ----------------------
extern "C" void kernel_launch(void* const* d_in, const int* in_sizes, int n_in,
                              void* d_out, int out_size) {
    const float* inputs   = (const float*)d_in[0];
    const float* codebook = (const float*)d_in[1];
    const float* ccounts  = (const float*)d_in[2];
    const int*   train    = (const int*)d_in[3];
    float* out = (float*)d_out;

    static bool attr_set = false;
    if (!attr_set) {
        cudaFuncSetAttribute(vq_gemm_mma, cudaFuncAttributeMaxDynamicSharedMemorySize, GSM_TOTAL);
        attr_set = true;
    }

    vq_quant<<<2304, 256>>>(inputs, codebook);   // 18432 warps = 16384 A + 2048 B
    vq_init<<<64, 256>>>();
    vq_gemm_mma<<<dim3(K_CENT / GBN, N_ROWS / GBM), 256, GSM_TOTAL>>>();
    vq_softmax<<<NBLK_SM, 256>>>();
    vq_refine<<<N_ROWS / 8, 256>>>(inputs, codebook, out + OFF_IDX, out + OFF_Q);
    vq_div_reduce<<<dim3(8, 16), 256>>>();
    vq_finalize<<<1, 256>>>(ccounts, train, out + OFF_CNT);
    vq_fill<<<8192, 256>>>(out + OFF_LOSS);
    cudaMemcpyAsync(out + OFF_CB, d_in[1], (size_t)K_CENT * D_DIM * sizeof(float),
                    cudaMemcpyDeviceToDevice, 0);
    (void)in_sizes; (void)n_in; (void)out_size;
}

// round 11
// speedup vs baseline: 1.7884x; 1.5733x over previous
#include <cuda_runtime.h>
#include <cuda_bf16.h>
#include <cstdint>
#include <cstddef>

// Problem constants
#define N_ROWS   16384
#define D_DIM    512
#define K_CENT   2048
#define EMA      0.99f
#define GAMMAF   1.0f
#define EPSF     1e-8f
#define DELTA    1.5e-2f
#define ROWS_PER_BLK 16
#define NBLK_SM  (N_ROWS / ROWS_PER_BLK)   // 1024

// Output layout (float32, concatenated in reference return order)
#define OFF_Q    ((size_t)0)
#define OFF_LOSS ((size_t)8388608)
#define OFF_IDX  ((size_t)41943040)
#define OFF_CB   ((size_t)41959424)
#define OFF_CNT  ((size_t)43008000)

// ---------------- scratch (static device memory) -----------------------------
__device__ __align__(16) __nv_bfloat16 g_simh[(size_t)N_ROWS * K_CENT];   // 67 MB
__device__ float g_div_part[(size_t)NBLK_SM * K_CENT];    // 8 MB
__device__ float g_div2[16 * K_CENT];
__device__ float g_h_part[NBLK_SM];
__device__ int   g_counts[K_CENT];
__device__ float g_loss;
__device__ int   g_cand[(size_t)N_ROWS * 32];             // 2 MB
__device__ int   g_ncand[N_ROWS];
__device__ __align__(16) __nv_bfloat16 g_Abf[(size_t)N_ROWS * D_DIM];  // 16.8 MB
__device__ __align__(16) __nv_bfloat16 g_Bbf[(size_t)K_CENT * D_DIM];  // 2 MB

__device__ __forceinline__ uint32_t smem_u32(const void* p) {
    uint32_t a;
    asm("{ .reg .u64 t; cvta.to.shared.u64 t, %1; cvt.u32.u64 %0, t; }" : "=r"(a) : "l"(p));
    return a;
}

// ---------------- kernel: fp32 -> bf16 convert + counter reset ----------------
__global__ __launch_bounds__(256)
void vq_convert(const float* __restrict__ A, const float* __restrict__ B) {
    const size_t NA4 = (size_t)N_ROWS * D_DIM / 4;   // 2097152
    const size_t NB4 = (size_t)K_CENT * D_DIM / 4;   // 262144
    size_t i = (size_t)blockIdx.x * 256 + threadIdx.x;
    if (i < N_ROWS) g_ncand[i] = 0;                  // fused init
    if (i < K_CENT) g_counts[i] = 0;
    if (i >= NA4 + NB4) return;
    const bool isA = (i < NA4);
    const float4 x = isA ? ((const float4*)A)[i] : ((const float4*)B)[i - NA4];
    __nv_bfloat162 lo = __floats2bfloat162_rn(x.x, x.y);
    __nv_bfloat162 hi = __floats2bfloat162_rn(x.z, x.w);
    size_t e = (isA ? i : (i - NA4));
    __nv_bfloat162* d = (__nv_bfloat162*)(isA ? g_Abf : g_Bbf);
    d[e * 2]     = lo;
    d[e * 2 + 1] = hi;
}

// ---------------- kernel: mma.sync bf16 GEMM  sim = A @ B^T ------------------
// tile 128(M) x 256(N), BK=32, 3-stage cp.async pipeline
#define GBM 128
#define GBN 256
#define GSTAGE_BYTES 30720        // A 128x80B=10240 + B 256x80B=20480
#define GSM_TOTAL (3 * GSTAGE_BYTES)   // 92160
#define NKSTEP 16                 // 512 / 32

__device__ __forceinline__ void g_load_stage(uint32_t smemU, int st, int kstep,
                                             int m0, int n0, int tid) {
    const int kin = kstep * 32;
    const uint32_t sA = smemU + st * GSTAGE_BYTES;
    const uint32_t sB = sA + 10240;
#pragma unroll
    for (int h = 0; h < 6; h++) {
        const int c = tid + h * 256;            // 0..1535
        if (c < 512) {
            const int row = c >> 2, q = c & 3;
            const void* src = g_Abf + (size_t)(m0 + row) * D_DIM + kin + q * 8;
            const uint32_t dst = sA + row * 80 + q * 16;
            asm volatile("cp.async.cg.shared.global [%0], [%1], 16;" :: "r"(dst), "l"(src));
        } else {
            const int c2 = c - 512;
            const int row = c2 >> 2, q = c2 & 3;
            const void* src = g_Bbf + (size_t)(n0 + row) * D_DIM + kin + q * 8;
            const uint32_t dst = sB + row * 80 + q * 16;
            asm volatile("cp.async.cg.shared.global [%0], [%1], 16;" :: "r"(dst), "l"(src));
        }
    }
}

__global__ __launch_bounds__(256, 1)
void vq_gemm_mma() {
    extern __shared__ char gsm[];
    const uint32_t smemU = smem_u32(gsm);
    const int tid = threadIdx.x;
    const int lane = tid & 31;
    const int w = tid >> 5;
    const int wm = (w & 1) * 64;       // warp m-offset (2 warps in M)
    const int wn = (w >> 1) * 64;      // warp n-offset (4 warps in N)
    const int n0 = blockIdx.x * GBN;
    const int m0 = blockIdx.y * GBM;

    float acc[4][8][4];
#pragma unroll
    for (int a = 0; a < 4; a++)
#pragma unroll
        for (int b = 0; b < 8; b++)
#pragma unroll
            for (int c = 0; c < 4; c++) acc[a][b][c] = 0.f;

    g_load_stage(smemU, 0, 0, m0, n0, tid);
    asm volatile("cp.async.commit_group;" ::: "memory");
    g_load_stage(smemU, 1, 1, m0, n0, tid);
    asm volatile("cp.async.commit_group;" ::: "memory");

    int st = 0, ls = 2;
    for (int i = 0; i < NKSTEP; i++) {
        if (i + 2 < NKSTEP) asm volatile("cp.async.wait_group 1;" ::: "memory");
        else                asm volatile("cp.async.wait_group 0;" ::: "memory");
        __syncthreads();
        if (i + 2 < NKSTEP) {
            g_load_stage(smemU, ls, i + 2, m0, n0, tid);
            asm volatile("cp.async.commit_group;" ::: "memory");
            ls = (ls == 2) ? 0 : ls + 1;
        }
        const uint32_t sA = smemU + st * GSTAGE_BYTES;
        const uint32_t sB = sA + 10240;
#pragma unroll
        for (int k16 = 0; k16 < 32; k16 += 16) {
            uint32_t a[4][4], b[4][4];
#pragma unroll
            for (int mt = 0; mt < 4; mt++) {
                const uint32_t addr = sA + (wm + mt * 16 + (lane & 15)) * 80
                                         + (k16 + ((lane >> 4) << 3)) * 2;
                asm volatile("ldmatrix.sync.aligned.m8n8.x4.shared.b16 {%0,%1,%2,%3}, [%4];"
                    : "=r"(a[mt][0]), "=r"(a[mt][1]), "=r"(a[mt][2]), "=r"(a[mt][3])
                    : "r"(addr));
            }
#pragma unroll
            for (int nt2 = 0; nt2 < 4; nt2++) {
                const uint32_t addr = sB + (wn + nt2 * 16 + ((lane >> 4) & 1) * 8 + (lane & 7)) * 80
                                         + (k16 + ((lane >> 3) & 1) * 8) * 2;
                asm volatile("ldmatrix.sync.aligned.m8n8.x4.shared.b16 {%0,%1,%2,%3}, [%4];"
                    : "=r"(b[nt2][0]), "=r"(b[nt2][1]), "=r"(b[nt2][2]), "=r"(b[nt2][3])
                    : "r"(addr));
            }
#pragma unroll
            for (int mt = 0; mt < 4; mt++)
#pragma unroll
                for (int nt = 0; nt < 8; nt++) {
                    asm volatile(
                        "mma.sync.aligned.m16n8k16.row.col.f32.bf16.bf16.f32 "
                        "{%0,%1,%2,%3},{%4,%5,%6,%7},{%8,%9},{%0,%1,%2,%3};"
                        : "+f"(acc[mt][nt][0]), "+f"(acc[mt][nt][1]),
                          "+f"(acc[mt][nt][2]), "+f"(acc[mt][nt][3])
                        : "r"(a[mt][0]), "r"(a[mt][1]), "r"(a[mt][2]), "r"(a[mt][3]),
                          "r"(b[nt >> 1][(nt & 1) * 2]), "r"(b[nt >> 1][(nt & 1) * 2 + 1]));
                }
        }
        st = (st == 2) ? 0 : st + 1;
    }

    // epilogue: bf16 stores
#pragma unroll
    for (int mt = 0; mt < 4; mt++) {
        const int r0 = m0 + wm + mt * 16 + (lane >> 2);
        const int cb = n0 + wn + (lane & 3) * 2;
#pragma unroll
        for (int nt = 0; nt < 8; nt++) {
            __nv_bfloat16* p0 = g_simh + (size_t)r0 * K_CENT + cb + nt * 8;
            __nv_bfloat16* p1 = p0 + (size_t)8 * K_CENT;
            *(__nv_bfloat162*)p0 = __floats2bfloat162_rn(acc[mt][nt][0], acc[mt][nt][1]);
            *(__nv_bfloat162*)p1 = __floats2bfloat162_rn(acc[mt][nt][2], acc[mt][nt][3]);
        }
    }
}

// ---------------- kernel: softmax / candidates / entropy / diversity ---------
// thread t owns columns [8t, 8t+8) of every row; diversity partials in registers
__global__ __launch_bounds__(256)
void vq_softmax() {
    __shared__ float warr[8], wS[8], wT[8];
    const int t = threadIdx.x;
    const int lane = t & 31;
    const int w = t >> 5;
    const int row0 = blockIdx.x * ROWS_PER_BLK;

    float pdiv[8];
#pragma unroll
    for (int j = 0; j < 8; j++) pdiv[j] = 0.f;
    float hacc = 0.f;

    for (int r = 0; r < ROWS_PER_BLK; ++r) {
        const int n = row0 + r;
        const uint4 raw = ((const uint4*)g_simh)[(size_t)n * (K_CENT / 8) + t];
        float v[8];
        {
            const __nv_bfloat162* h2 = (const __nv_bfloat162*)&raw;
#pragma unroll
            for (int p = 0; p < 4; p++) {
                float2 f = __bfloat1622float2(h2[p]);
                v[p * 2] = f.x; v[p * 2 + 1] = f.y;
            }
        }

        float mv = v[0];
#pragma unroll
        for (int j = 1; j < 8; j++) mv = fmaxf(mv, v[j]);
#pragma unroll
        for (int o = 16; o > 0; o >>= 1) mv = fmaxf(mv, __shfl_xor_sync(0xffffffffu, mv, o));
        if (lane == 0) warr[w] = mv;
        __syncthreads();
        float rowmax = warr[0];
#pragma unroll
        for (int k = 1; k < 8; k++) rowmax = fmaxf(rowmax, warr[k]);

        // candidates within DELTA of approx max -> global list (order-independent winner)
#pragma unroll
        for (int j = 0; j < 8; j++) {
            if (v[j] >= rowmax - DELTA) {
                int s = atomicAdd(&g_ncand[n], 1);
                if (s < 32) g_cand[(size_t)n * 32 + s] = t * 8 + j;
            }
        }

        float e[8], ls = 0.f, ts = 0.f;
#pragma unroll
        for (int j = 0; j < 8; j++) {
            float u = v[j] - rowmax;
            float ee = __expf(u);
            e[j] = ee; ls += ee; ts += ee * u;
        }
#pragma unroll
        for (int o = 16; o > 0; o >>= 1) {
            ls += __shfl_xor_sync(0xffffffffu, ls, o);
            ts += __shfl_xor_sync(0xffffffffu, ts, o);
        }
        if (lane == 0) { wS[w] = ls; wT[w] = ts; }
        __syncthreads();
        float S = 0.f, T = 0.f;
#pragma unroll
        for (int k = 0; k < 8; k++) { S += wS[k]; T += wT[k]; }
        const float invS = 1.0f / S;

#pragma unroll
        for (int j = 0; j < 8; j++) pdiv[j] += e[j] * invS;
        // sum_k p*log2(p) = log2e*(T/S) - log2(S)
        if (t == 0) hacc += 1.44269504f * (T * invS) - __log2f(S);
    }

    float* dp = g_div_part + (size_t)blockIdx.x * K_CENT + t * 8;
    *(float4*)(dp)     = make_float4(pdiv[0], pdiv[1], pdiv[2], pdiv[3]);
    *(float4*)(dp + 4) = make_float4(pdiv[4], pdiv[5], pdiv[6], pdiv[7]);
    if (t == 0) g_h_part[blockIdx.x] = hacc;
}

// ---------------- kernel: exact argmax refine + counts + quantize (fused) ----
// one warp per row; decision numerics frozen (exact fp32 dot, (max, min-idx))
__global__ __launch_bounds__(256)
void vq_refine(const float* __restrict__ inputs, const float* __restrict__ codebook,
               float* __restrict__ out_idx, float* __restrict__ out_q) {
    const int t = threadIdx.x;
    const int lane = t & 31;
    const int w = t >> 5;
    const int n = blockIdx.x * 8 + w;

    const int nc = min(g_ncand[n], 32);
    float bestv = -3.4e38f; int besti = 0x7fffffff;
    const float4* ar = (const float4*)(inputs + (size_t)n * D_DIM);
    for (int c = 0; c < nc; ++c) {
        const int k = g_cand[(size_t)n * 32 + c];
        const float4* br = (const float4*)(codebook + (size_t)k * D_DIM);
        float part = 0.f;
#pragma unroll 4
        for (int i = lane; i < D_DIM / 4; i += 32) {
            float4 a = ar[i], b = br[i];
            part += a.x * b.x + a.y * b.y + a.z * b.z + a.w * b.w;
        }
#pragma unroll
        for (int o = 16; o > 0; o >>= 1)
            part += __shfl_xor_sync(0xffffffffu, part, o);
        if (part > bestv || (part == bestv && k < besti)) { bestv = part; besti = k; }
    }
    if (lane == 0) {
        out_idx[n] = (float)besti;
        atomicAdd(&g_counts[besti], 1);
    }

    // fused quantize: center, normalize, STE
    const float4* br = (const float4*)(codebook + (size_t)besti * D_DIM);
    float4 q[4];
    float s = 0.f;
#pragma unroll
    for (int i = 0; i < 4; i++) {
        q[i] = br[lane + 32 * i];
        s += q[i].x + q[i].y + q[i].z + q[i].w;
    }
#pragma unroll
    for (int o = 16; o > 0; o >>= 1) s += __shfl_xor_sync(0xffffffffu, s, o);
    const float mean = s * (1.0f / (float)D_DIM);

    float ss = 0.f;
#pragma unroll
    for (int i = 0; i < 4; i++) {
        q[i].x -= mean; q[i].y -= mean; q[i].z -= mean; q[i].w -= mean;
        ss += q[i].x * q[i].x + q[i].y * q[i].y + q[i].z * q[i].z + q[i].w * q[i].w;
    }
#pragma unroll
    for (int o = 16; o > 0; o >>= 1) ss += __shfl_xor_sync(0xffffffffu, ss, o);
    const float inv = 1.0f / sqrtf(ss);

    float4* oq = (float4*)(out_q + (size_t)n * D_DIM);
#pragma unroll
    for (int i = 0; i < 4; i++) {
        const float4 x = ar[lane + 32 * i];
        float4 o;
        o.x = x.x + (q[i].x * inv - x.x);
        o.y = x.y + (q[i].y * inv - x.y);
        o.z = x.z + (q[i].z * inv - x.z);
        o.w = x.w + (q[i].w * inv - x.w);
        oq[lane + 32 * i] = o;
    }
}

// ---------------- kernel: deterministic diversity reduction ------------------
__global__ __launch_bounds__(256)
void vq_div_reduce() {
    const int k = blockIdx.x * 256 + threadIdx.x;  // 0..2047 (gridDim.x = 8)
    const int chunk = blockIdx.y;                  // 0..15
    const int b0 = chunk * 64;
    float s0 = 0.f, s1 = 0.f, s2 = 0.f, s3 = 0.f;
    for (int b = 0; b < 64; b += 4) {
        s0 += g_div_part[(size_t)(b0 + b + 0) * K_CENT + k];
        s1 += g_div_part[(size_t)(b0 + b + 1) * K_CENT + k];
        s2 += g_div_part[(size_t)(b0 + b + 2) * K_CENT + k];
        s3 += g_div_part[(size_t)(b0 + b + 3) * K_CENT + k];
    }
    g_div2[chunk * K_CENT + k] = (s0 + s1) + (s2 + s3);
}

// ---------------- kernel: finalize loss + EMA counts -------------------------
__global__ __launch_bounds__(256)
void vq_finalize(const float* __restrict__ cluster_counts,
                 const int* __restrict__ train,
                 float* __restrict__ out_counts) {
    __shared__ float redf[256];
    const int t = threadIdx.x;
    const int tr = train[0];

    float hdiv = 0.f;
    for (int k = t; k < K_CENT; k += 256) {
        float s = 0.f;
#pragma unroll
        for (int ch = 0; ch < 16; ch++) s += g_div2[ch * K_CENT + k];
        float d = s * (1.0f / (float)N_ROWS);
        hdiv += d * __log2f(d + EPSF);
        float cnt = (float)g_counts[k];
        float oc  = cluster_counts[k];
        out_counts[k] = tr ? (EMA * oc + (1.0f - EMA) * cnt) : oc;
    }
    float hsum = 0.f;
    for (int i = t; i < NBLK_SM; i += 256) hsum += g_h_part[i];

    redf[t] = hdiv;
    __syncthreads();
    for (int s = 128; s > 0; s >>= 1) { if (t < s) redf[t] += redf[t + s]; __syncthreads(); }
    const float hdiv_tot = redf[0];
    __syncthreads();
    redf[t] = hsum;
    __syncthreads();
    for (int s = 128; s > 0; s >>= 1) { if (t < s) redf[t] += redf[t + s]; __syncthreads(); }
    if (t == 0) {
        float h_clust     = -(redf[0] / (float)N_ROWS);
        float h_diversity = -hdiv_tot;
        g_loss = h_clust - GAMMAF * h_diversity;
    }
}

// ---------------- kernel: broadcast-fill quantization_loss -------------------
// one contiguous float4 per thread, grid-wide coalesced streaming writes
__global__ __launch_bounds__(256)
void vq_fill(float* __restrict__ dst) {
    const float v = g_loss;
    const float4 f = make_float4(v, v, v, v);
    const size_t i = (size_t)blockIdx.x * 256 + threadIdx.x;   // 32768*256 = 8388608
    ((float4*)dst)[i] = f;
}

// ---------------- launcher (single stream) ------------------------------------
extern "C" void kernel_launch(void* const* d_in, const int* in_sizes, int n_in,
                              void* d_out, int out_size) {
    const float* inputs   = (const float*)d_in[0];
    const float* codebook = (const float*)d_in[1];
    const float* ccounts  = (const float*)d_in[2];
    const int*   train    = (const int*)d_in[3];
    float* out = (float*)d_out;

    static bool attr_set = false;
    if (!attr_set) {
        cudaFuncSetAttribute(vq_gemm_mma, cudaFuncAttributeMaxDynamicSharedMemorySize, GSM_TOTAL);
        attr_set = true;
    }

    vq_convert<<<9216, 256>>>(inputs, codebook);   // also resets g_ncand/g_counts
    vq_gemm_mma<<<dim3(K_CENT / GBN, N_ROWS / GBM), 256, GSM_TOTAL>>>();
    vq_softmax<<<NBLK_SM, 256>>>();
    vq_refine<<<N_ROWS / 8, 256>>>(inputs, codebook, out + OFF_IDX, out + OFF_Q);
    vq_div_reduce<<<dim3(8, 16), 256>>>();
    vq_finalize<<<1, 256>>>(ccounts, train, out + OFF_CNT);
    vq_fill<<<32768, 256>>>(out + OFF_LOSS);
    cudaMemcpyAsync(out + OFF_CB, d_in[1], (size_t)K_CENT * D_DIM * sizeof(float),
                    cudaMemcpyDeviceToDevice, 0);
    (void)in_sizes; (void)n_in; (void)out_size;
}

// round 12
// speedup vs baseline: 1.8724x; 1.0470x over previous
#include <cuda_runtime.h>
#include <cuda_bf16.h>
#include <cstdint>
#include <cstddef>

// Problem constants
#define N_ROWS   16384
#define D_DIM    512
#define K_CENT   2048
#define EMA      0.99f
#define GAMMAF   1.0f
#define EPSF     1e-8f
#define DELTA    1.5e-2f
#define ROWS_PER_BLK 16
#define NBLK_SM  (N_ROWS / ROWS_PER_BLK)   // 1024

// Output layout (float32, concatenated in reference return order)
#define OFF_Q    ((size_t)0)
#define OFF_LOSS ((size_t)8388608)
#define OFF_IDX  ((size_t)41943040)
#define OFF_CB   ((size_t)41959424)
#define OFF_CNT  ((size_t)43008000)

// ---------------- scratch (static device memory) -----------------------------
__device__ __align__(16) __nv_bfloat16 g_simh[(size_t)N_ROWS * K_CENT];   // 67 MB
__device__ float g_div_part[(size_t)NBLK_SM * K_CENT];    // 8 MB
__device__ float g_div2[16 * K_CENT];
__device__ float g_h_part[NBLK_SM];
__device__ int   g_counts[K_CENT];
__device__ float g_loss;
__device__ int   g_cand[(size_t)N_ROWS * 32];             // 2 MB
__device__ int   g_ncand[N_ROWS];
__device__ __align__(16) __nv_bfloat16 g_Abf[(size_t)N_ROWS * D_DIM];  // 16.8 MB
__device__ __align__(16) __nv_bfloat16 g_Bbf[(size_t)K_CENT * D_DIM];  // 2 MB

__device__ __forceinline__ uint32_t smem_u32(const void* p) {
    uint32_t a;
    asm("{ .reg .u64 t; cvta.to.shared.u64 t, %1; cvt.u32.u64 %0, t; }" : "=r"(a) : "l"(p));
    return a;
}

// ---------------- kernel: fp32 -> bf16 convert + counter reset ----------------
__global__ __launch_bounds__(256)
void vq_convert(const float* __restrict__ A, const float* __restrict__ B) {
    const size_t NA4 = (size_t)N_ROWS * D_DIM / 4;   // 2097152
    const size_t NB4 = (size_t)K_CENT * D_DIM / 4;   // 262144
    size_t i = (size_t)blockIdx.x * 256 + threadIdx.x;
    if (i < N_ROWS) g_ncand[i] = 0;                  // fused init
    if (i < K_CENT) g_counts[i] = 0;
    if (i >= NA4 + NB4) return;
    const bool isA = (i < NA4);
    const float4 x = isA ? ((const float4*)A)[i] : ((const float4*)B)[i - NA4];
    __nv_bfloat162 lo = __floats2bfloat162_rn(x.x, x.y);
    __nv_bfloat162 hi = __floats2bfloat162_rn(x.z, x.w);
    size_t e = (isA ? i : (i - NA4));
    __nv_bfloat162* d = (__nv_bfloat162*)(isA ? g_Abf : g_Bbf);
    d[e * 2]     = lo;
    d[e * 2 + 1] = hi;
}

// ---------------- kernel: mma.sync bf16 GEMM  sim = A @ B^T ------------------
// tile 128(M) x 256(N), BK=32, 3-stage cp.async pipeline
#define GBM 128
#define GBN 256
#define GSTAGE_BYTES 30720        // A 128x80B=10240 + B 256x80B=20480
#define GSM_TOTAL (3 * GSTAGE_BYTES)   // 92160
#define NKSTEP 16                 // 512 / 32

__device__ __forceinline__ void g_load_stage(uint32_t smemU, int st, int kstep,
                                             int m0, int n0, int tid) {
    const int kin = kstep * 32;
    const uint32_t sA = smemU + st * GSTAGE_BYTES;
    const uint32_t sB = sA + 10240;
#pragma unroll
    for (int h = 0; h < 6; h++) {
        const int c = tid + h * 256;            // 0..1535
        if (c < 512) {
            const int row = c >> 2, q = c & 3;
            const void* src = g_Abf + (size_t)(m0 + row) * D_DIM + kin + q * 8;
            const uint32_t dst = sA + row * 80 + q * 16;
            asm volatile("cp.async.cg.shared.global [%0], [%1], 16;" :: "r"(dst), "l"(src));
        } else {
            const int c2 = c - 512;
            const int row = c2 >> 2, q = c2 & 3;
            const void* src = g_Bbf + (size_t)(n0 + row) * D_DIM + kin + q * 8;
            const uint32_t dst = sB + row * 80 + q * 16;
            asm volatile("cp.async.cg.shared.global [%0], [%1], 16;" :: "r"(dst), "l"(src));
        }
    }
}

__global__ __launch_bounds__(256, 1)
void vq_gemm_mma() {
    extern __shared__ char gsm[];
    const uint32_t smemU = smem_u32(gsm);
    const int tid = threadIdx.x;
    const int lane = tid & 31;
    const int w = tid >> 5;
    const int wm = (w & 1) * 64;       // warp m-offset (2 warps in M)
    const int wn = (w >> 1) * 64;      // warp n-offset (4 warps in N)
    const int n0 = blockIdx.x * GBN;
    const int m0 = blockIdx.y * GBM;

    float acc[4][8][4];
#pragma unroll
    for (int a = 0; a < 4; a++)
#pragma unroll
        for (int b = 0; b < 8; b++)
#pragma unroll
            for (int c = 0; c < 4; c++) acc[a][b][c] = 0.f;

    g_load_stage(smemU, 0, 0, m0, n0, tid);
    asm volatile("cp.async.commit_group;" ::: "memory");
    g_load_stage(smemU, 1, 1, m0, n0, tid);
    asm volatile("cp.async.commit_group;" ::: "memory");

    int st = 0, ls = 2;
    for (int i = 0; i < NKSTEP; i++) {
        if (i + 2 < NKSTEP) asm volatile("cp.async.wait_group 1;" ::: "memory");
        else                asm volatile("cp.async.wait_group 0;" ::: "memory");
        __syncthreads();
        if (i + 2 < NKSTEP) {
            g_load_stage(smemU, ls, i + 2, m0, n0, tid);
            asm volatile("cp.async.commit_group;" ::: "memory");
            ls = (ls == 2) ? 0 : ls + 1;
        }
        const uint32_t sA = smemU + st * GSTAGE_BYTES;
        const uint32_t sB = sA + 10240;
#pragma unroll
        for (int k16 = 0; k16 < 32; k16 += 16) {
            uint32_t a[4][4], b[4][4];
#pragma unroll
            for (int mt = 0; mt < 4; mt++) {
                const uint32_t addr = sA + (wm + mt * 16 + (lane & 15)) * 80
                                         + (k16 + ((lane >> 4) << 3)) * 2;
                asm volatile("ldmatrix.sync.aligned.m8n8.x4.shared.b16 {%0,%1,%2,%3}, [%4];"
                    : "=r"(a[mt][0]), "=r"(a[mt][1]), "=r"(a[mt][2]), "=r"(a[mt][3])
                    : "r"(addr));
            }
#pragma unroll
            for (int nt2 = 0; nt2 < 4; nt2++) {
                const uint32_t addr = sB + (wn + nt2 * 16 + ((lane >> 4) & 1) * 8 + (lane & 7)) * 80
                                         + (k16 + ((lane >> 3) & 1) * 8) * 2;
                asm volatile("ldmatrix.sync.aligned.m8n8.x4.shared.b16 {%0,%1,%2,%3}, [%4];"
                    : "=r"(b[nt2][0]), "=r"(b[nt2][1]), "=r"(b[nt2][2]), "=r"(b[nt2][3])
                    : "r"(addr));
            }
#pragma unroll
            for (int mt = 0; mt < 4; mt++)
#pragma unroll
                for (int nt = 0; nt < 8; nt++) {
                    asm volatile(
                        "mma.sync.aligned.m16n8k16.row.col.f32.bf16.bf16.f32 "
                        "{%0,%1,%2,%3},{%4,%5,%6,%7},{%8,%9},{%0,%1,%2,%3};"
                        : "+f"(acc[mt][nt][0]), "+f"(acc[mt][nt][1]),
                          "+f"(acc[mt][nt][2]), "+f"(acc[mt][nt][3])
                        : "r"(a[mt][0]), "r"(a[mt][1]), "r"(a[mt][2]), "r"(a[mt][3]),
                          "r"(b[nt >> 1][(nt & 1) * 2]), "r"(b[nt >> 1][(nt & 1) * 2 + 1]));
                }
        }
        st = (st == 2) ? 0 : st + 1;
    }

    // epilogue: bf16 stores
#pragma unroll
    for (int mt = 0; mt < 4; mt++) {
        const int r0 = m0 + wm + mt * 16 + (lane >> 2);
        const int cb = n0 + wn + (lane & 3) * 2;
#pragma unroll
        for (int nt = 0; nt < 8; nt++) {
            __nv_bfloat16* p0 = g_simh + (size_t)r0 * K_CENT + cb + nt * 8;
            __nv_bfloat16* p1 = p0 + (size_t)8 * K_CENT;
            *(__nv_bfloat162*)p0 = __floats2bfloat162_rn(acc[mt][nt][0], acc[mt][nt][1]);
            *(__nv_bfloat162*)p1 = __floats2bfloat162_rn(acc[mt][nt][2], acc[mt][nt][3]);
        }
    }
}

// ---------------- kernel: softmax / candidates / entropy / diversity ---------
// thread t owns columns [8t, 8t+8); TWO rows processed per iteration so the
// max-barrier of row r+1 shares the sync slot with the sum-barrier of row r.
// Per-row arithmetic order is IDENTICAL to the R7/R11 kernel -> bit-identical.
__global__ __launch_bounds__(256)
void vq_softmax() {
    __shared__ float warr[2][8], wS[2][8], wT[2][8];
    const int t = threadIdx.x;
    const int lane = t & 31;
    const int w = t >> 5;
    const int row0 = blockIdx.x * ROWS_PER_BLK;

    float pdiv[8];
#pragma unroll
    for (int j = 0; j < 8; j++) pdiv[j] = 0.f;
    float hacc = 0.f;

    for (int rp = 0; rp < ROWS_PER_BLK; rp += 2) {
        const int n0 = row0 + rp;
        const int n1 = n0 + 1;
        // load both rows
        const uint4 raw0 = ((const uint4*)g_simh)[(size_t)n0 * (K_CENT / 8) + t];
        const uint4 raw1 = ((const uint4*)g_simh)[(size_t)n1 * (K_CENT / 8) + t];
        float v0[8], v1[8];
        {
            const __nv_bfloat162* h0 = (const __nv_bfloat162*)&raw0;
            const __nv_bfloat162* h1 = (const __nv_bfloat162*)&raw1;
#pragma unroll
            for (int p = 0; p < 4; p++) {
                float2 f0 = __bfloat1622float2(h0[p]);
                float2 f1 = __bfloat1622float2(h1[p]);
                v0[p * 2] = f0.x; v0[p * 2 + 1] = f0.y;
                v1[p * 2] = f1.x; v1[p * 2 + 1] = f1.y;
            }
        }

        // interleaved local + warp max for both rows (hides shfl latency)
        float m0 = v0[0], m1 = v1[0];
#pragma unroll
        for (int j = 1; j < 8; j++) { m0 = fmaxf(m0, v0[j]); m1 = fmaxf(m1, v1[j]); }
#pragma unroll
        for (int o = 16; o > 0; o >>= 1) {
            m0 = fmaxf(m0, __shfl_xor_sync(0xffffffffu, m0, o));
            m1 = fmaxf(m1, __shfl_xor_sync(0xffffffffu, m1, o));
        }
        if (lane == 0) { warr[0][w] = m0; warr[1][w] = m1; }
        __syncthreads();
        float rowmax0 = warr[0][0], rowmax1 = warr[1][0];
#pragma unroll
        for (int k = 1; k < 8; k++) {
            rowmax0 = fmaxf(rowmax0, warr[0][k]);
            rowmax1 = fmaxf(rowmax1, warr[1][k]);
        }

        // candidates (order-independent winner; same predicate as before)
#pragma unroll
        for (int j = 0; j < 8; j++) {
            if (v0[j] >= rowmax0 - DELTA) {
                int s = atomicAdd(&g_ncand[n0], 1);
                if (s < 32) g_cand[(size_t)n0 * 32 + s] = t * 8 + j;
            }
            if (v1[j] >= rowmax1 - DELTA) {
                int s = atomicAdd(&g_ncand[n1], 1);
                if (s < 32) g_cand[(size_t)n1 * 32 + s] = t * 8 + j;
            }
        }

        float e0[8], e1[8];
        float ls0 = 0.f, ts0 = 0.f, ls1 = 0.f, ts1 = 0.f;
#pragma unroll
        for (int j = 0; j < 8; j++) {
            float u0 = v0[j] - rowmax0;
            float u1 = v1[j] - rowmax1;
            float ee0 = __expf(u0);
            float ee1 = __expf(u1);
            e0[j] = ee0; ls0 += ee0; ts0 += ee0 * u0;
            e1[j] = ee1; ls1 += ee1; ts1 += ee1 * u1;
        }
#pragma unroll
        for (int o = 16; o > 0; o >>= 1) {
            ls0 += __shfl_xor_sync(0xffffffffu, ls0, o);
            ts0 += __shfl_xor_sync(0xffffffffu, ts0, o);
            ls1 += __shfl_xor_sync(0xffffffffu, ls1, o);
            ts1 += __shfl_xor_sync(0xffffffffu, ts1, o);
        }
        if (lane == 0) { wS[0][w] = ls0; wT[0][w] = ts0; wS[1][w] = ls1; wT[1][w] = ts1; }
        __syncthreads();
        float S0 = 0.f, T0 = 0.f, S1 = 0.f, T1 = 0.f;
#pragma unroll
        for (int k = 0; k < 8; k++) {
            S0 += wS[0][k]; T0 += wT[0][k];
            S1 += wS[1][k]; T1 += wT[1][k];
        }
        const float invS0 = 1.0f / S0;
        const float invS1 = 1.0f / S1;

#pragma unroll
        for (int j = 0; j < 8; j++) {
            pdiv[j] += e0[j] * invS0;
            pdiv[j] += e1[j] * invS1;
        }
        // sum_k p*log2(p) = log2e*(T/S) - log2(S), accumulated per row in order
        if (t == 0) {
            hacc += 1.44269504f * (T0 * invS0) - __log2f(S0);
            hacc += 1.44269504f * (T1 * invS1) - __log2f(S1);
        }
    }

    float* dp = g_div_part + (size_t)blockIdx.x * K_CENT + t * 8;
    *(float4*)(dp)     = make_float4(pdiv[0], pdiv[1], pdiv[2], pdiv[3]);
    *(float4*)(dp + 4) = make_float4(pdiv[4], pdiv[5], pdiv[6], pdiv[7]);
    if (t == 0) g_h_part[blockIdx.x] = hacc;
}

// ---------------- kernel: exact argmax refine + counts + quantize (fused) ----
// one warp per row; decision numerics frozen (exact fp32 dot, (max, min-idx))
__global__ __launch_bounds__(256)
void vq_refine(const float* __restrict__ inputs, const float* __restrict__ codebook,
               float* __restrict__ out_idx, float* __restrict__ out_q) {
    const int t = threadIdx.x;
    const int lane = t & 31;
    const int w = t >> 5;
    const int n = blockIdx.x * 8 + w;

    const int nc = min(g_ncand[n], 32);
    float bestv = -3.4e38f; int besti = 0x7fffffff;
    const float4* ar = (const float4*)(inputs + (size_t)n * D_DIM);
    for (int c = 0; c < nc; ++c) {
        const int k = g_cand[(size_t)n * 32 + c];
        const float4* br = (const float4*)(codebook + (size_t)k * D_DIM);
        float part = 0.f;
#pragma unroll 4
        for (int i = lane; i < D_DIM / 4; i += 32) {
            float4 a = ar[i], b = br[i];
            part += a.x * b.x + a.y * b.y + a.z * b.z + a.w * b.w;
        }
#pragma unroll
        for (int o = 16; o > 0; o >>= 1)
            part += __shfl_xor_sync(0xffffffffu, part, o);
        if (part > bestv || (part == bestv && k < besti)) { bestv = part; besti = k; }
    }
    if (lane == 0) {
        out_idx[n] = (float)besti;
        atomicAdd(&g_counts[besti], 1);
    }

    // fused quantize: center, normalize, STE
    const float4* br = (const float4*)(codebook + (size_t)besti * D_DIM);
    float4 q[4];
    float s = 0.f;
#pragma unroll
    for (int i = 0; i < 4; i++) {
        q[i] = br[lane + 32 * i];
        s += q[i].x + q[i].y + q[i].z + q[i].w;
    }
#pragma unroll
    for (int o = 16; o > 0; o >>= 1) s += __shfl_xor_sync(0xffffffffu, s, o);
    const float mean = s * (1.0f / (float)D_DIM);

    float ss = 0.f;
#pragma unroll
    for (int i = 0; i < 4; i++) {
        q[i].x -= mean; q[i].y -= mean; q[i].z -= mean; q[i].w -= mean;
        ss += q[i].x * q[i].x + q[i].y * q[i].y + q[i].z * q[i].z + q[i].w * q[i].w;
    }
#pragma unroll
    for (int o = 16; o > 0; o >>= 1) ss += __shfl_xor_sync(0xffffffffu, ss, o);
    const float inv = 1.0f / sqrtf(ss);

    float4* oq = (float4*)(out_q + (size_t)n * D_DIM);
#pragma unroll
    for (int i = 0; i < 4; i++) {
        const float4 x = ar[lane + 32 * i];
        float4 o;
        o.x = x.x + (q[i].x * inv - x.x);
        o.y = x.y + (q[i].y * inv - x.y);
        o.z = x.z + (q[i].z * inv - x.z);
        o.w = x.w + (q[i].w * inv - x.w);
        oq[lane + 32 * i] = o;
    }
}

// ---------------- kernel: deterministic diversity reduction ------------------
__global__ __launch_bounds__(256)
void vq_div_reduce() {
    const int k = blockIdx.x * 256 + threadIdx.x;  // 0..2047 (gridDim.x = 8)
    const int chunk = blockIdx.y;                  // 0..15
    const int b0 = chunk * 64;
    float s0 = 0.f, s1 = 0.f, s2 = 0.f, s3 = 0.f;
    for (int b = 0; b < 64; b += 4) {
        s0 += g_div_part[(size_t)(b0 + b + 0) * K_CENT + k];
        s1 += g_div_part[(size_t)(b0 + b + 1) * K_CENT + k];
        s2 += g_div_part[(size_t)(b0 + b + 2) * K_CENT + k];
        s3 += g_div_part[(size_t)(b0 + b + 3) * K_CENT + k];
    }
    g_div2[chunk * K_CENT + k] = (s0 + s1) + (s2 + s3);
}

// ---------------- kernel: finalize loss + EMA counts -------------------------
__global__ __launch_bounds__(256)
void vq_finalize(const float* __restrict__ cluster_counts,
                 const int* __restrict__ train,
                 float* __restrict__ out_counts) {
    __shared__ float redf[256];
    const int t = threadIdx.x;
    const int tr = train[0];

    float hdiv = 0.f;
    for (int k = t; k < K_CENT; k += 256) {
        float s = 0.f;
#pragma unroll
        for (int ch = 0; ch < 16; ch++) s += g_div2[ch * K_CENT + k];
        float d = s * (1.0f / (float)N_ROWS);
        hdiv += d * __log2f(d + EPSF);
        float cnt = (float)g_counts[k];
        float oc  = cluster_counts[k];
        out_counts[k] = tr ? (EMA * oc + (1.0f - EMA) * cnt) : oc;
    }
    float hsum = 0.f;
    for (int i = t; i < NBLK_SM; i += 256) hsum += g_h_part[i];

    redf[t] = hdiv;
    __syncthreads();
    for (int s = 128; s > 0; s >>= 1) { if (t < s) redf[t] += redf[t + s]; __syncthreads(); }
    const float hdiv_tot = redf[0];
    __syncthreads();
    redf[t] = hsum;
    __syncthreads();
    for (int s = 128; s > 0; s >>= 1) { if (t < s) redf[t] += redf[t + s]; __syncthreads(); }
    if (t == 0) {
        float h_clust     = -(redf[0] / (float)N_ROWS);
        float h_diversity = -hdiv_tot;
        g_loss = h_clust - GAMMAF * h_diversity;
    }
}

// ---------------- kernel: loss broadcast-fill + codebook copy (fused) --------
// blocks [0, 2048): fill 33554432 loss floats (4096 float4 per block, coalesced)
// blocks [2048, 2112): copy 1048576 codebook floats (262144 float4)
__global__ __launch_bounds__(256)
void vq_fill(float* __restrict__ loss_dst, float* __restrict__ cb_dst,
             const float* __restrict__ cb_src) {
    const int b = blockIdx.x;
    const int t = threadIdx.x;
    if (b < 2048) {
        const float v = g_loss;
        const float4 f = make_float4(v, v, v, v);
        float4* dst = (float4*)loss_dst + (size_t)b * 4096 + t;
#pragma unroll
        for (int j = 0; j < 16; j++)
            dst[j * 256] = f;
    } else {
        const size_t base = (size_t)(b - 2048) * 4096 + t;
        const float4* src = (const float4*)cb_src;
        float4* dst = (float4*)cb_dst;
#pragma unroll
        for (int j = 0; j < 16; j++)
            dst[base + j * 256] = src[base + j * 256];
    }
}

// ---------------- launcher (single stream) ------------------------------------
extern "C" void kernel_launch(void* const* d_in, const int* in_sizes, int n_in,
                              void* d_out, int out_size) {
    const float* inputs   = (const float*)d_in[0];
    const float* codebook = (const float*)d_in[1];
    const float* ccounts  = (const float*)d_in[2];
    const int*   train    = (const int*)d_in[3];
    float* out = (float*)d_out;

    static bool attr_set = false;
    if (!attr_set) {
        cudaFuncSetAttribute(vq_gemm_mma, cudaFuncAttributeMaxDynamicSharedMemorySize, GSM_TOTAL);
        attr_set = true;
    }

    vq_convert<<<9216, 256>>>(inputs, codebook);   // also resets g_ncand/g_counts
    vq_gemm_mma<<<dim3(K_CENT / GBN, N_ROWS / GBM), 256, GSM_TOTAL>>>();
    vq_softmax<<<NBLK_SM, 256>>>();
    vq_refine<<<N_ROWS / 8, 256>>>(inputs, codebook, out + OFF_IDX, out + OFF_Q);
    vq_div_reduce<<<dim3(8, 16), 256>>>();
    vq_finalize<<<1, 256>>>(ccounts, train, out + OFF_CNT);
    vq_fill<<<2112, 256>>>(out + OFF_LOSS, out + OFF_CB, codebook);
    (void)in_sizes; (void)n_in; (void)out_size;
}

// round 16
// speedup vs baseline: 1.9147x; 1.0226x over previous
#include <cuda_runtime.h>
#include <cuda_bf16.h>
#include <cstdint>
#include <cstddef>

// Problem constants
#define N_ROWS   16384
#define D_DIM    512
#define K_CENT   2048
#define EMA      0.99f
#define GAMMAF   1.0f
#define EPSF     1e-8f
#define DELTA    1.5e-2f
#define ROWS_PER_BLK 16
#define NBLK_SM  (N_ROWS / ROWS_PER_BLK)   // 1024

// Output layout (float32, concatenated in reference return order)
#define OFF_Q    ((size_t)0)
#define OFF_LOSS ((size_t)8388608)
#define OFF_IDX  ((size_t)41943040)
#define OFF_CB   ((size_t)41959424)
#define OFF_CNT  ((size_t)43008000)

// ---------------- scratch (static device memory) -----------------------------
__device__ __align__(16) __nv_bfloat16 g_simh[(size_t)N_ROWS * K_CENT];   // 67 MB
__device__ float g_div_part[(size_t)NBLK_SM * K_CENT];    // 8 MB
__device__ float g_div2[16 * K_CENT];
__device__ float g_h_part[NBLK_SM];
__device__ int   g_counts[K_CENT];
__device__ float g_loss;
__device__ int   g_cand[(size_t)N_ROWS * 32];             // 2 MB
__device__ int   g_ncand[N_ROWS];
__device__ __align__(16) __nv_bfloat16 g_Abf[(size_t)N_ROWS * D_DIM];  // 16.8 MB
__device__ __align__(16) __nv_bfloat16 g_Bbf[(size_t)K_CENT * D_DIM];  // 2 MB

__device__ __forceinline__ uint32_t smem_u32(const void* p) {
    uint32_t a;
    asm("{ .reg .u64 t; cvta.to.shared.u64 t, %1; cvt.u32.u64 %0, t; }" : "=r"(a) : "l"(p));
    return a;
}

// ---------------- kernel: fp32 -> bf16 convert + counter reset ----------------
__global__ __launch_bounds__(256)
void vq_convert(const float* __restrict__ A, const float* __restrict__ B) {
    const size_t NA4 = (size_t)N_ROWS * D_DIM / 4;   // 2097152
    const size_t NB4 = (size_t)K_CENT * D_DIM / 4;   // 262144
    size_t i = (size_t)blockIdx.x * 256 + threadIdx.x;
    if (i < N_ROWS) g_ncand[i] = 0;                  // fused init
    if (i < K_CENT) g_counts[i] = 0;
    if (i >= NA4 + NB4) return;
    const bool isA = (i < NA4);
    const float4 x = isA ? ((const float4*)A)[i] : ((const float4*)B)[i - NA4];
    __nv_bfloat162 lo = __floats2bfloat162_rn(x.x, x.y);
    __nv_bfloat162 hi = __floats2bfloat162_rn(x.z, x.w);
    size_t e = (isA ? i : (i - NA4));
    __nv_bfloat162* d = (__nv_bfloat162*)(isA ? g_Abf : g_Bbf);
    d[e * 2]     = lo;
    d[e * 2 + 1] = hi;
}

// ---------------- kernel: mma.sync bf16 GEMM  sim = A @ B^T ------------------
// tile 128(M) x 256(N), BK=32, 3-stage cp.async pipeline
#define GBM 128
#define GBN 256
#define GSTAGE_BYTES 30720        // A 128x80B=10240 + B 256x80B=20480
#define GSM_TOTAL (3 * GSTAGE_BYTES)   // 92160
#define NKSTEP 16                 // 512 / 32

__device__ __forceinline__ void g_load_stage(uint32_t smemU, int st, int kstep,
                                             int m0, int n0, int tid) {
    const int kin = kstep * 32;
    const uint32_t sA = smemU + st * GSTAGE_BYTES;
    const uint32_t sB = sA + 10240;
#pragma unroll
    for (int h = 0; h < 6; h++) {
        const int c = tid + h * 256;            // 0..1535
        if (c < 512) {
            const int row = c >> 2, q = c & 3;
            const void* src = g_Abf + (size_t)(m0 + row) * D_DIM + kin + q * 8;
            const uint32_t dst = sA + row * 80 + q * 16;
            asm volatile("cp.async.cg.shared.global [%0], [%1], 16;" :: "r"(dst), "l"(src));
        } else {
            const int c2 = c - 512;
            const int row = c2 >> 2, q = c2 & 3;
            const void* src = g_Bbf + (size_t)(n0 + row) * D_DIM + kin + q * 8;
            const uint32_t dst = sB + row * 80 + q * 16;
            asm volatile("cp.async.cg.shared.global [%0], [%1], 16;" :: "r"(dst), "l"(src));
        }
    }
}

__global__ __launch_bounds__(256, 1)
void vq_gemm_mma() {
    extern __shared__ char gsm[];
    const uint32_t smemU = smem_u32(gsm);
    const int tid = threadIdx.x;
    const int lane = tid & 31;
    const int w = tid >> 5;
    const int wm = (w & 1) * 64;       // warp m-offset (2 warps in M)
    const int wn = (w >> 1) * 64;      // warp n-offset (4 warps in N)
    const int n0 = blockIdx.x * GBN;
    const int m0 = blockIdx.y * GBM;

    float acc[4][8][4];
#pragma unroll
    for (int a = 0; a < 4; a++)
#pragma unroll
        for (int b = 0; b < 8; b++)
#pragma unroll
            for (int c = 0; c < 4; c++) acc[a][b][c] = 0.f;

    g_load_stage(smemU, 0, 0, m0, n0, tid);
    asm volatile("cp.async.commit_group;" ::: "memory");
    g_load_stage(smemU, 1, 1, m0, n0, tid);
    asm volatile("cp.async.commit_group;" ::: "memory");

    int st = 0, ls = 2;
    for (int i = 0; i < NKSTEP; i++) {
        if (i + 2 < NKSTEP) asm volatile("cp.async.wait_group 1;" ::: "memory");
        else                asm volatile("cp.async.wait_group 0;" ::: "memory");
        __syncthreads();
        if (i + 2 < NKSTEP) {
            g_load_stage(smemU, ls, i + 2, m0, n0, tid);
            asm volatile("cp.async.commit_group;" ::: "memory");
            ls = (ls == 2) ? 0 : ls + 1;
        }
        const uint32_t sA = smemU + st * GSTAGE_BYTES;
        const uint32_t sB = sA + 10240;
#pragma unroll
        for (int k16 = 0; k16 < 32; k16 += 16) {
            uint32_t a[4][4], b[4][4];
#pragma unroll
            for (int mt = 0; mt < 4; mt++) {
                const uint32_t addr = sA + (wm + mt * 16 + (lane & 15)) * 80
                                         + (k16 + ((lane >> 4) << 3)) * 2;
                asm volatile("ldmatrix.sync.aligned.m8n8.x4.shared.b16 {%0,%1,%2,%3}, [%4];"
                    : "=r"(a[mt][0]), "=r"(a[mt][1]), "=r"(a[mt][2]), "=r"(a[mt][3])
                    : "r"(addr));
            }
#pragma unroll
            for (int nt2 = 0; nt2 < 4; nt2++) {
                const uint32_t addr = sB + (wn + nt2 * 16 + ((lane >> 4) & 1) * 8 + (lane & 7)) * 80
                                         + (k16 + ((lane >> 3) & 1) * 8) * 2;
                asm volatile("ldmatrix.sync.aligned.m8n8.x4.shared.b16 {%0,%1,%2,%3}, [%4];"
                    : "=r"(b[nt2][0]), "=r"(b[nt2][1]), "=r"(b[nt2][2]), "=r"(b[nt2][3])
                    : "r"(addr));
            }
#pragma unroll
            for (int mt = 0; mt < 4; mt++)
#pragma unroll
                for (int nt = 0; nt < 8; nt++) {
                    asm volatile(
                        "mma.sync.aligned.m16n8k16.row.col.f32.bf16.bf16.f32 "
                        "{%0,%1,%2,%3},{%4,%5,%6,%7},{%8,%9},{%0,%1,%2,%3};"
                        : "+f"(acc[mt][nt][0]), "+f"(acc[mt][nt][1]),
                          "+f"(acc[mt][nt][2]), "+f"(acc[mt][nt][3])
                        : "r"(a[mt][0]), "r"(a[mt][1]), "r"(a[mt][2]), "r"(a[mt][3]),
                          "r"(b[nt >> 1][(nt & 1) * 2]), "r"(b[nt >> 1][(nt & 1) * 2 + 1]));
                }
        }
        st = (st == 2) ? 0 : st + 1;
    }

    // epilogue: bf16 stores
#pragma unroll
    for (int mt = 0; mt < 4; mt++) {
        const int r0 = m0 + wm + mt * 16 + (lane >> 2);
        const int cb = n0 + wn + (lane & 3) * 2;
#pragma unroll
        for (int nt = 0; nt < 8; nt++) {
            __nv_bfloat16* p0 = g_simh + (size_t)r0 * K_CENT + cb + nt * 8;
            __nv_bfloat16* p1 = p0 + (size_t)8 * K_CENT;
            *(__nv_bfloat162*)p0 = __floats2bfloat162_rn(acc[mt][nt][0], acc[mt][nt][1]);
            *(__nv_bfloat162*)p1 = __floats2bfloat162_rn(acc[mt][nt][2], acc[mt][nt][3]);
        }
    }
}

// ---------------- kernel: softmax (R12 bit-exact; two rows per iteration) ----
__global__ __launch_bounds__(256)
void vq_softmax() {
    __shared__ float warr[2][8], wS[2][8], wT[2][8];
    const int t = threadIdx.x;
    const int lane = t & 31;
    const int w = t >> 5;
    const int row0 = blockIdx.x * ROWS_PER_BLK;

    float pdiv[8];
#pragma unroll
    for (int j = 0; j < 8; j++) pdiv[j] = 0.f;
    float hacc = 0.f;

    for (int rp = 0; rp < ROWS_PER_BLK; rp += 2) {
        const int n0 = row0 + rp;
        const int n1 = n0 + 1;
        const uint4 raw0 = ((const uint4*)g_simh)[(size_t)n0 * (K_CENT / 8) + t];
        const uint4 raw1 = ((const uint4*)g_simh)[(size_t)n1 * (K_CENT / 8) + t];
        float v0[8], v1[8];
        {
            const __nv_bfloat162* h0 = (const __nv_bfloat162*)&raw0;
            const __nv_bfloat162* h1 = (const __nv_bfloat162*)&raw1;
#pragma unroll
            for (int p = 0; p < 4; p++) {
                float2 f0 = __bfloat1622float2(h0[p]);
                float2 f1 = __bfloat1622float2(h1[p]);
                v0[p * 2] = f0.x; v0[p * 2 + 1] = f0.y;
                v1[p * 2] = f1.x; v1[p * 2 + 1] = f1.y;
            }
        }

        float m0 = v0[0], m1 = v1[0];
#pragma unroll
        for (int j = 1; j < 8; j++) { m0 = fmaxf(m0, v0[j]); m1 = fmaxf(m1, v1[j]); }
#pragma unroll
        for (int o = 16; o > 0; o >>= 1) {
            m0 = fmaxf(m0, __shfl_xor_sync(0xffffffffu, m0, o));
            m1 = fmaxf(m1, __shfl_xor_sync(0xffffffffu, m1, o));
        }
        if (lane == 0) { warr[0][w] = m0; warr[1][w] = m1; }
        __syncthreads();
        float rowmax0 = warr[0][0], rowmax1 = warr[1][0];
#pragma unroll
        for (int k = 1; k < 8; k++) {
            rowmax0 = fmaxf(rowmax0, warr[0][k]);
            rowmax1 = fmaxf(rowmax1, warr[1][k]);
        }

#pragma unroll
        for (int j = 0; j < 8; j++) {
            if (v0[j] >= rowmax0 - DELTA) {
                int s = atomicAdd(&g_ncand[n0], 1);
                if (s < 32) g_cand[(size_t)n0 * 32 + s] = t * 8 + j;
            }
            if (v1[j] >= rowmax1 - DELTA) {
                int s = atomicAdd(&g_ncand[n1], 1);
                if (s < 32) g_cand[(size_t)n1 * 32 + s] = t * 8 + j;
            }
        }

        float e0[8], e1[8];
        float ls0 = 0.f, ts0 = 0.f, ls1 = 0.f, ts1 = 0.f;
#pragma unroll
        for (int j = 0; j < 8; j++) {
            float u0 = v0[j] - rowmax0;
            float u1 = v1[j] - rowmax1;
            float ee0 = __expf(u0);
            float ee1 = __expf(u1);
            e0[j] = ee0; ls0 += ee0; ts0 += ee0 * u0;
            e1[j] = ee1; ls1 += ee1; ts1 += ee1 * u1;
        }
#pragma unroll
        for (int o = 16; o > 0; o >>= 1) {
            ls0 += __shfl_xor_sync(0xffffffffu, ls0, o);
            ts0 += __shfl_xor_sync(0xffffffffu, ts0, o);
            ls1 += __shfl_xor_sync(0xffffffffu, ls1, o);
            ts1 += __shfl_xor_sync(0xffffffffu, ts1, o);
        }
        if (lane == 0) { wS[0][w] = ls0; wT[0][w] = ts0; wS[1][w] = ls1; wT[1][w] = ts1; }
        __syncthreads();
        float S0 = 0.f, T0 = 0.f, S1 = 0.f, T1 = 0.f;
#pragma unroll
        for (int k = 0; k < 8; k++) {
            S0 += wS[0][k]; T0 += wT[0][k];
            S1 += wS[1][k]; T1 += wT[1][k];
        }
        const float invS0 = 1.0f / S0;
        const float invS1 = 1.0f / S1;

#pragma unroll
        for (int j = 0; j < 8; j++) {
            pdiv[j] += e0[j] * invS0;
            pdiv[j] += e1[j] * invS1;
        }
        if (t == 0) {
            hacc += 1.44269504f * (T0 * invS0) - __log2f(S0);
            hacc += 1.44269504f * (T1 * invS1) - __log2f(S1);
        }
    }

    float* dp = g_div_part + (size_t)blockIdx.x * K_CENT + t * 8;
    *(float4*)(dp)     = make_float4(pdiv[0], pdiv[1], pdiv[2], pdiv[3]);
    *(float4*)(dp + 4) = make_float4(pdiv[4], pdiv[5], pdiv[6], pdiv[7]);
    if (t == 0) g_h_part[blockIdx.x] = hacc;
}

// ---------------- kernel: exact argmax refine + counts + quantize (fused) ----
// one warp per row; candidate-dot order frozen -> besti unchanged
__global__ __launch_bounds__(256)
void vq_refine(const float* __restrict__ inputs, const float* __restrict__ codebook,
               float* __restrict__ out_idx, float* __restrict__ out_q) {
    const int t = threadIdx.x;
    const int lane = t & 31;
    const int w = t >> 5;
    const int n = blockIdx.x * 8 + w;

    const float4* ar = (const float4*)(inputs + (size_t)n * D_DIM);
    float4 x0 = ar[lane], x1 = ar[lane + 32], x2 = ar[lane + 64], x3 = ar[lane + 96];

    const int nc = min(g_ncand[n], 32);
    float bestv = -3.4e38f; int besti = 0x7fffffff;
    for (int c = 0; c < nc; ++c) {
        const int k = g_cand[(size_t)n * 32 + c];
        const float4* br = (const float4*)(codebook + (size_t)k * D_DIM);
        float part = 0.f;
        {
            float4 b = br[lane];
            part += x0.x * b.x + x0.y * b.y + x0.z * b.z + x0.w * b.w;
            b = br[lane + 32];
            part += x1.x * b.x + x1.y * b.y + x1.z * b.z + x1.w * b.w;
            b = br[lane + 64];
            part += x2.x * b.x + x2.y * b.y + x2.z * b.z + x2.w * b.w;
            b = br[lane + 96];
            part += x3.x * b.x + x3.y * b.y + x3.z * b.z + x3.w * b.w;
        }
#pragma unroll
        for (int o = 16; o > 0; o >>= 1)
            part += __shfl_xor_sync(0xffffffffu, part, o);
        if (part > bestv || (part == bestv && k < besti)) { bestv = part; besti = k; }
    }
    if (lane == 0) {
        out_idx[n] = (float)besti;
        atomicAdd(&g_counts[besti], 1);
    }

    // fused quantize: single interleaved reduction for sum and sumsq
    const float4* br = (const float4*)(codebook + (size_t)besti * D_DIM);
    float4 q[4];
    float s = 0.f, ss = 0.f;
#pragma unroll
    for (int i = 0; i < 4; i++) {
        q[i] = br[lane + 32 * i];
        s  += q[i].x + q[i].y + q[i].z + q[i].w;
        ss += q[i].x * q[i].x + q[i].y * q[i].y + q[i].z * q[i].z + q[i].w * q[i].w;
    }
#pragma unroll
    for (int o = 16; o > 0; o >>= 1) {
        s  += __shfl_xor_sync(0xffffffffu, s, o);
        ss += __shfl_xor_sync(0xffffffffu, ss, o);
    }
    const float mean = s * (1.0f / (float)D_DIM);
    const float norm2 = ss - s * mean;       // sum(q^2) - sum(q)^2/D
    const float inv = 1.0f / sqrtf(norm2);

    float4 xs[4] = {x0, x1, x2, x3};
    float4* oq = (float4*)(out_q + (size_t)n * D_DIM);
#pragma unroll
    for (int i = 0; i < 4; i++) {
        const float4 x = xs[i];
        float4 o;
        o.x = x.x + ((q[i].x - mean) * inv - x.x);
        o.y = x.y + ((q[i].y - mean) * inv - x.y);
        o.z = x.z + ((q[i].z - mean) * inv - x.z);
        o.w = x.w + ((q[i].w - mean) * inv - x.w);
        oq[lane + 32 * i] = o;
    }
}

// ---------------- kernel: deterministic diversity reduction (R12 exact) ------
__global__ __launch_bounds__(256)
void vq_div_reduce() {
    const int k = blockIdx.x * 256 + threadIdx.x;  // 0..2047 (gridDim.x = 8)
    const int chunk = blockIdx.y;                  // 0..15
    const int b0 = chunk * 64;
    float s0 = 0.f, s1 = 0.f, s2 = 0.f, s3 = 0.f;
    for (int b = 0; b < 64; b += 4) {
        s0 += g_div_part[(size_t)(b0 + b + 0) * K_CENT + k];
        s1 += g_div_part[(size_t)(b0 + b + 1) * K_CENT + k];
        s2 += g_div_part[(size_t)(b0 + b + 2) * K_CENT + k];
        s3 += g_div_part[(size_t)(b0 + b + 3) * K_CENT + k];
    }
    g_div2[chunk * K_CENT + k] = (s0 + s1) + (s2 + s3);
}

// ---------------- kernel: finalize loss + EMA counts (R12 exact) -------------
__global__ __launch_bounds__(256)
void vq_finalize(const float* __restrict__ cluster_counts,
                 const int* __restrict__ train,
                 float* __restrict__ out_counts) {
    __shared__ float redf[256];
    const int t = threadIdx.x;
    const int tr = train[0];

    float hdiv = 0.f;
    for (int k = t; k < K_CENT; k += 256) {
        float s = 0.f;
#pragma unroll
        for (int ch = 0; ch < 16; ch++) s += g_div2[ch * K_CENT + k];
        float d = s * (1.0f / (float)N_ROWS);
        hdiv += d * __log2f(d + EPSF);
        float cnt = (float)g_counts[k];
        float oc  = cluster_counts[k];
        out_counts[k] = tr ? (EMA * oc + (1.0f - EMA) * cnt) : oc;
    }
    float hsum = 0.f;
    for (int i = t; i < NBLK_SM; i += 256) hsum += g_h_part[i];

    redf[t] = hdiv;
    __syncthreads();
    for (int s = 128; s > 0; s >>= 1) { if (t < s) redf[t] += redf[t + s]; __syncthreads(); }
    const float hdiv_tot = redf[0];
    __syncthreads();
    redf[t] = hsum;
    __syncthreads();
    for (int s = 128; s > 0; s >>= 1) { if (t < s) redf[t] += redf[t + s]; __syncthreads(); }
    if (t == 0) {
        float h_clust     = -(redf[0] / (float)N_ROWS);
        float h_diversity = -hdiv_tot;
        g_loss = h_clust - GAMMAF * h_diversity;
    }
}

// ---------------- kernel: loss broadcast-fill + codebook copy (fused) --------
__global__ __launch_bounds__(256)
void vq_fill(float* __restrict__ loss_dst, float* __restrict__ cb_dst,
             const float* __restrict__ cb_src) {
    const int b = blockIdx.x;
    const int t = threadIdx.x;
    if (b < 2048) {
        const float v = g_loss;
        const float4 f = make_float4(v, v, v, v);
        float4* dst = (float4*)loss_dst + (size_t)b * 4096 + t;
#pragma unroll
        for (int j = 0; j < 16; j++)
            dst[j * 256] = f;
    } else {
        const size_t base = (size_t)(b - 2048) * 4096 + t;
        const float4* src = (const float4*)cb_src;
        float4* dst = (float4*)cb_dst;
#pragma unroll
        for (int j = 0; j < 16; j++)
            dst[base + j * 256] = src[base + j * 256];
    }
}

// ---------------- launcher: main chain + refine forked on s2 ------------------
extern "C" void kernel_launch(void* const* d_in, const int* in_sizes, int n_in,
                              void* d_out, int out_size) {
    const float* inputs   = (const float*)d_in[0];
    const float* codebook = (const float*)d_in[1];
    const float* ccounts  = (const float*)d_in[2];
    const int*   train    = (const int*)d_in[3];
    float* out = (float*)d_out;

    static bool inited = false;
    static cudaStream_t s2;
    static cudaEvent_t evS, evR;
    if (!inited) {
        cudaFuncSetAttribute(vq_gemm_mma, cudaFuncAttributeMaxDynamicSharedMemorySize, GSM_TOTAL);
        cudaStreamCreateWithFlags(&s2, cudaStreamNonBlocking);
        cudaEventCreateWithFlags(&evS, cudaEventDisableTiming);
        cudaEventCreateWithFlags(&evR, cudaEventDisableTiming);
        inited = true;
    }

    vq_convert<<<9216, 256>>>(inputs, codebook);   // also resets g_ncand/g_counts
    vq_gemm_mma<<<dim3(K_CENT / GBN, N_ROWS / GBM), 256, GSM_TOTAL>>>();
    vq_softmax<<<NBLK_SM, 256>>>();
    cudaEventRecord(evS, 0);

    // fork: refine (argmax + quantize + counts) on s2, overlapping div_reduce
    cudaStreamWaitEvent(s2, evS, 0);
    vq_refine<<<N_ROWS / 8, 256, 0, s2>>>(inputs, codebook, out + OFF_IDX, out + OFF_Q);
    cudaEventRecord(evR, s2);

    vq_div_reduce<<<dim3(8, 16), 256>>>();
    cudaStreamWaitEvent(0, evR, 0);                // finalize needs g_counts
    vq_finalize<<<1, 256>>>(ccounts, train, out + OFF_CNT);
    vq_fill<<<2112, 256>>>(out + OFF_LOSS, out + OFF_CB, codebook);
    (void)in_sizes; (void)n_in; (void)out_size;
}

// round 17
// speedup vs baseline: 1.9237x; 1.0047x over previous
#include <cuda_runtime.h>
#include <cuda_bf16.h>
#include <cstdint>
#include <cstddef>

// Problem constants
#define N_ROWS   16384
#define D_DIM    512
#define K_CENT   2048
#define EMA      0.99f
#define GAMMAF   1.0f
#define EPSF     1e-8f
#define DELTA    1.5e-2f
#define ROWS_PER_BLK 16
#define NBLK_SM  (N_ROWS / ROWS_PER_BLK)   // 1024

// Output layout (float32, concatenated in reference return order)
#define OFF_Q    ((size_t)0)
#define OFF_LOSS ((size_t)8388608)
#define OFF_IDX  ((size_t)41943040)
#define OFF_CB   ((size_t)41959424)
#define OFF_CNT  ((size_t)43008000)

// ---------------- scratch (static device memory) -----------------------------
__device__ __align__(16) __nv_bfloat16 g_simh[(size_t)N_ROWS * K_CENT];   // 67 MB
__device__ float g_div_part[(size_t)NBLK_SM * K_CENT];    // 8 MB
__device__ float g_div2[16 * K_CENT];
__device__ float g_h_part[NBLK_SM];
__device__ int   g_counts[K_CENT];
__device__ float g_loss;
__device__ int   g_cand[(size_t)N_ROWS * 32];             // 2 MB
__device__ int   g_ncand[N_ROWS];
__device__ __align__(16) __nv_bfloat16 g_Abf[(size_t)N_ROWS * D_DIM];  // 16.8 MB
__device__ __align__(16) __nv_bfloat16 g_Bbf[(size_t)K_CENT * D_DIM];  // 2 MB

__device__ __forceinline__ uint32_t smem_u32(const void* p) {
    uint32_t a;
    asm("{ .reg .u64 t; cvta.to.shared.u64 t, %1; cvt.u32.u64 %0, t; }" : "=r"(a) : "l"(p));
    return a;
}

// ---------------- kernel: fp32 -> bf16 convert + counter reset ----------------
__global__ __launch_bounds__(256)
void vq_convert(const float* __restrict__ A, const float* __restrict__ B) {
    const size_t NA4 = (size_t)N_ROWS * D_DIM / 4;   // 2097152
    const size_t NB4 = (size_t)K_CENT * D_DIM / 4;   // 262144
    size_t i = (size_t)blockIdx.x * 256 + threadIdx.x;
    if (i < N_ROWS) g_ncand[i] = 0;                  // fused init
    if (i < K_CENT) g_counts[i] = 0;
    if (i >= NA4 + NB4) return;
    const bool isA = (i < NA4);
    const float4 x = isA ? ((const float4*)A)[i] : ((const float4*)B)[i - NA4];
    __nv_bfloat162 lo = __floats2bfloat162_rn(x.x, x.y);
    __nv_bfloat162 hi = __floats2bfloat162_rn(x.z, x.w);
    size_t e = (isA ? i : (i - NA4));
    __nv_bfloat162* d = (__nv_bfloat162*)(isA ? g_Abf : g_Bbf);
    d[e * 2]     = lo;
    d[e * 2 + 1] = hi;
}

// ---------------- kernel: mma.sync bf16 GEMM  sim = A @ B^T ------------------
// tile 128(M) x 256(N), BK=32, 3-stage cp.async pipeline
#define GBM 128
#define GBN 256
#define GSTAGE_BYTES 30720        // A 128x80B=10240 + B 256x80B=20480
#define GSM_TOTAL (3 * GSTAGE_BYTES)   // 92160
#define NKSTEP 16                 // 512 / 32

__device__ __forceinline__ void g_load_stage(uint32_t smemU, int st, int kstep,
                                             int m0, int n0, int tid) {
    const int kin = kstep * 32;
    const uint32_t sA = smemU + st * GSTAGE_BYTES;
    const uint32_t sB = sA + 10240;
#pragma unroll
    for (int h = 0; h < 6; h++) {
        const int c = tid + h * 256;            // 0..1535
        if (c < 512) {
            const int row = c >> 2, q = c & 3;
            const void* src = g_Abf + (size_t)(m0 + row) * D_DIM + kin + q * 8;
            const uint32_t dst = sA + row * 80 + q * 16;
            asm volatile("cp.async.cg.shared.global [%0], [%1], 16;" :: "r"(dst), "l"(src));
        } else {
            const int c2 = c - 512;
            const int row = c2 >> 2, q = c2 & 3;
            const void* src = g_Bbf + (size_t)(n0 + row) * D_DIM + kin + q * 8;
            const uint32_t dst = sB + row * 80 + q * 16;
            asm volatile("cp.async.cg.shared.global [%0], [%1], 16;" :: "r"(dst), "l"(src));
        }
    }
}

__global__ __launch_bounds__(256, 1)
void vq_gemm_mma() {
    extern __shared__ char gsm[];
    const uint32_t smemU = smem_u32(gsm);
    const int tid = threadIdx.x;
    const int lane = tid & 31;
    const int w = tid >> 5;
    const int wm = (w & 1) * 64;       // warp m-offset (2 warps in M)
    const int wn = (w >> 1) * 64;      // warp n-offset (4 warps in N)
    const int n0 = blockIdx.x * GBN;
    const int m0 = blockIdx.y * GBM;

    float acc[4][8][4];
#pragma unroll
    for (int a = 0; a < 4; a++)
#pragma unroll
        for (int b = 0; b < 8; b++)
#pragma unroll
            for (int c = 0; c < 4; c++) acc[a][b][c] = 0.f;

    g_load_stage(smemU, 0, 0, m0, n0, tid);
    asm volatile("cp.async.commit_group;" ::: "memory");
    g_load_stage(smemU, 1, 1, m0, n0, tid);
    asm volatile("cp.async.commit_group;" ::: "memory");

    int st = 0, ls = 2;
    for (int i = 0; i < NKSTEP; i++) {
        if (i + 2 < NKSTEP) asm volatile("cp.async.wait_group 1;" ::: "memory");
        else                asm volatile("cp.async.wait_group 0;" ::: "memory");
        __syncthreads();
        if (i + 2 < NKSTEP) {
            g_load_stage(smemU, ls, i + 2, m0, n0, tid);
            asm volatile("cp.async.commit_group;" ::: "memory");
            ls = (ls == 2) ? 0 : ls + 1;
        }
        const uint32_t sA = smemU + st * GSTAGE_BYTES;
        const uint32_t sB = sA + 10240;
#pragma unroll
        for (int k16 = 0; k16 < 32; k16 += 16) {
            uint32_t a[4][4], b[4][4];
#pragma unroll
            for (int mt = 0; mt < 4; mt++) {
                const uint32_t addr = sA + (wm + mt * 16 + (lane & 15)) * 80
                                         + (k16 + ((lane >> 4) << 3)) * 2;
                asm volatile("ldmatrix.sync.aligned.m8n8.x4.shared.b16 {%0,%1,%2,%3}, [%4];"
                    : "=r"(a[mt][0]), "=r"(a[mt][1]), "=r"(a[mt][2]), "=r"(a[mt][3])
                    : "r"(addr));
            }
#pragma unroll
            for (int nt2 = 0; nt2 < 4; nt2++) {
                const uint32_t addr = sB + (wn + nt2 * 16 + ((lane >> 4) & 1) * 8 + (lane & 7)) * 80
                                         + (k16 + ((lane >> 3) & 1) * 8) * 2;
                asm volatile("ldmatrix.sync.aligned.m8n8.x4.shared.b16 {%0,%1,%2,%3}, [%4];"
                    : "=r"(b[nt2][0]), "=r"(b[nt2][1]), "=r"(b[nt2][2]), "=r"(b[nt2][3])
                    : "r"(addr));
            }
#pragma unroll
            for (int mt = 0; mt < 4; mt++)
#pragma unroll
                for (int nt = 0; nt < 8; nt++) {
                    asm volatile(
                        "mma.sync.aligned.m16n8k16.row.col.f32.bf16.bf16.f32 "
                        "{%0,%1,%2,%3},{%4,%5,%6,%7},{%8,%9},{%0,%1,%2,%3};"
                        : "+f"(acc[mt][nt][0]), "+f"(acc[mt][nt][1]),
                          "+f"(acc[mt][nt][2]), "+f"(acc[mt][nt][3])
                        : "r"(a[mt][0]), "r"(a[mt][1]), "r"(a[mt][2]), "r"(a[mt][3]),
                          "r"(b[nt >> 1][(nt & 1) * 2]), "r"(b[nt >> 1][(nt & 1) * 2 + 1]));
                }
        }
        st = (st == 2) ? 0 : st + 1;
    }

    // epilogue: bf16 stores
#pragma unroll
    for (int mt = 0; mt < 4; mt++) {
        const int r0 = m0 + wm + mt * 16 + (lane >> 2);
        const int cb = n0 + wn + (lane & 3) * 2;
#pragma unroll
        for (int nt = 0; nt < 8; nt++) {
            __nv_bfloat16* p0 = g_simh + (size_t)r0 * K_CENT + cb + nt * 8;
            __nv_bfloat16* p1 = p0 + (size_t)8 * K_CENT;
            *(__nv_bfloat162*)p0 = __floats2bfloat162_rn(acc[mt][nt][0], acc[mt][nt][1]);
            *(__nv_bfloat162*)p1 = __floats2bfloat162_rn(acc[mt][nt][2], acc[mt][nt][3]);
        }
    }
}

// ---------------- kernel: softmax (R12 bit-exact; two rows per iteration) ----
__global__ __launch_bounds__(256)
void vq_softmax() {
    __shared__ float warr[2][8], wS[2][8], wT[2][8];
    const int t = threadIdx.x;
    const int lane = t & 31;
    const int w = t >> 5;
    const int row0 = blockIdx.x * ROWS_PER_BLK;

    float pdiv[8];
#pragma unroll
    for (int j = 0; j < 8; j++) pdiv[j] = 0.f;
    float hacc = 0.f;

    for (int rp = 0; rp < ROWS_PER_BLK; rp += 2) {
        const int n0 = row0 + rp;
        const int n1 = n0 + 1;
        const uint4 raw0 = ((const uint4*)g_simh)[(size_t)n0 * (K_CENT / 8) + t];
        const uint4 raw1 = ((const uint4*)g_simh)[(size_t)n1 * (K_CENT / 8) + t];
        float v0[8], v1[8];
        {
            const __nv_bfloat162* h0 = (const __nv_bfloat162*)&raw0;
            const __nv_bfloat162* h1 = (const __nv_bfloat162*)&raw1;
#pragma unroll
            for (int p = 0; p < 4; p++) {
                float2 f0 = __bfloat1622float2(h0[p]);
                float2 f1 = __bfloat1622float2(h1[p]);
                v0[p * 2] = f0.x; v0[p * 2 + 1] = f0.y;
                v1[p * 2] = f1.x; v1[p * 2 + 1] = f1.y;
            }
        }

        float m0 = v0[0], m1 = v1[0];
#pragma unroll
        for (int j = 1; j < 8; j++) { m0 = fmaxf(m0, v0[j]); m1 = fmaxf(m1, v1[j]); }
#pragma unroll
        for (int o = 16; o > 0; o >>= 1) {
            m0 = fmaxf(m0, __shfl_xor_sync(0xffffffffu, m0, o));
            m1 = fmaxf(m1, __shfl_xor_sync(0xffffffffu, m1, o));
        }
        if (lane == 0) { warr[0][w] = m0; warr[1][w] = m1; }
        __syncthreads();
        float rowmax0 = warr[0][0], rowmax1 = warr[1][0];
#pragma unroll
        for (int k = 1; k < 8; k++) {
            rowmax0 = fmaxf(rowmax0, warr[0][k]);
            rowmax1 = fmaxf(rowmax1, warr[1][k]);
        }

#pragma unroll
        for (int j = 0; j < 8; j++) {
            if (v0[j] >= rowmax0 - DELTA) {
                int s = atomicAdd(&g_ncand[n0], 1);
                if (s < 32) g_cand[(size_t)n0 * 32 + s] = t * 8 + j;
            }
            if (v1[j] >= rowmax1 - DELTA) {
                int s = atomicAdd(&g_ncand[n1], 1);
                if (s < 32) g_cand[(size_t)n1 * 32 + s] = t * 8 + j;
            }
        }

        float e0[8], e1[8];
        float ls0 = 0.f, ts0 = 0.f, ls1 = 0.f, ts1 = 0.f;
#pragma unroll
        for (int j = 0; j < 8; j++) {
            float u0 = v0[j] - rowmax0;
            float u1 = v1[j] - rowmax1;
            float ee0 = __expf(u0);
            float ee1 = __expf(u1);
            e0[j] = ee0; ls0 += ee0; ts0 += ee0 * u0;
            e1[j] = ee1; ls1 += ee1; ts1 += ee1 * u1;
        }
#pragma unroll
        for (int o = 16; o > 0; o >>= 1) {
            ls0 += __shfl_xor_sync(0xffffffffu, ls0, o);
            ts0 += __shfl_xor_sync(0xffffffffu, ts0, o);
            ls1 += __shfl_xor_sync(0xffffffffu, ls1, o);
            ts1 += __shfl_xor_sync(0xffffffffu, ts1, o);
        }
        if (lane == 0) { wS[0][w] = ls0; wT[0][w] = ts0; wS[1][w] = ls1; wT[1][w] = ts1; }
        __syncthreads();
        float S0 = 0.f, T0 = 0.f, S1 = 0.f, T1 = 0.f;
#pragma unroll
        for (int k = 0; k < 8; k++) {
            S0 += wS[0][k]; T0 += wT[0][k];
            S1 += wS[1][k]; T1 += wT[1][k];
        }
        const float invS0 = 1.0f / S0;
        const float invS1 = 1.0f / S1;

#pragma unroll
        for (int j = 0; j < 8; j++) {
            pdiv[j] += e0[j] * invS0;
            pdiv[j] += e1[j] * invS1;
        }
        if (t == 0) {
            hacc += 1.44269504f * (T0 * invS0) - __log2f(S0);
            hacc += 1.44269504f * (T1 * invS1) - __log2f(S1);
        }
    }

    float* dp = g_div_part + (size_t)blockIdx.x * K_CENT + t * 8;
    *(float4*)(dp)     = make_float4(pdiv[0], pdiv[1], pdiv[2], pdiv[3]);
    *(float4*)(dp + 4) = make_float4(pdiv[4], pdiv[5], pdiv[6], pdiv[7]);
    if (t == 0) g_h_part[blockIdx.x] = hacc;
}

// ---------------- kernel: exact argmax refine + counts + quantize (fused) ----
// one warp per row; candidate-dot order frozen -> besti unchanged
__global__ __launch_bounds__(256)
void vq_refine(const float* __restrict__ inputs, const float* __restrict__ codebook,
               float* __restrict__ out_idx, float* __restrict__ out_q) {
    const int t = threadIdx.x;
    const int lane = t & 31;
    const int w = t >> 5;
    const int n = blockIdx.x * 8 + w;

    const float4* ar = (const float4*)(inputs + (size_t)n * D_DIM);
    float4 x0 = ar[lane], x1 = ar[lane + 32], x2 = ar[lane + 64], x3 = ar[lane + 96];

    const int nc = min(g_ncand[n], 32);
    float bestv = -3.4e38f; int besti = 0x7fffffff;
    for (int c = 0; c < nc; ++c) {
        const int k = g_cand[(size_t)n * 32 + c];
        const float4* br = (const float4*)(codebook + (size_t)k * D_DIM);
        float part = 0.f;
        {
            float4 b = br[lane];
            part += x0.x * b.x + x0.y * b.y + x0.z * b.z + x0.w * b.w;
            b = br[lane + 32];
            part += x1.x * b.x + x1.y * b.y + x1.z * b.z + x1.w * b.w;
            b = br[lane + 64];
            part += x2.x * b.x + x2.y * b.y + x2.z * b.z + x2.w * b.w;
            b = br[lane + 96];
            part += x3.x * b.x + x3.y * b.y + x3.z * b.z + x3.w * b.w;
        }
#pragma unroll
        for (int o = 16; o > 0; o >>= 1)
            part += __shfl_xor_sync(0xffffffffu, part, o);
        if (part > bestv || (part == bestv && k < besti)) { bestv = part; besti = k; }
    }
    if (lane == 0) {
        out_idx[n] = (float)besti;
        atomicAdd(&g_counts[besti], 1);
    }

    // fused quantize: single interleaved reduction for sum and sumsq
    const float4* br = (const float4*)(codebook + (size_t)besti * D_DIM);
    float4 q[4];
    float s = 0.f, ss = 0.f;
#pragma unroll
    for (int i = 0; i < 4; i++) {
        q[i] = br[lane + 32 * i];
        s  += q[i].x + q[i].y + q[i].z + q[i].w;
        ss += q[i].x * q[i].x + q[i].y * q[i].y + q[i].z * q[i].z + q[i].w * q[i].w;
    }
#pragma unroll
    for (int o = 16; o > 0; o >>= 1) {
        s  += __shfl_xor_sync(0xffffffffu, s, o);
        ss += __shfl_xor_sync(0xffffffffu, ss, o);
    }
    const float mean = s * (1.0f / (float)D_DIM);
    const float norm2 = ss - s * mean;       // sum(q^2) - sum(q)^2/D
    const float inv = 1.0f / sqrtf(norm2);

    float4 xs[4] = {x0, x1, x2, x3};
    float4* oq = (float4*)(out_q + (size_t)n * D_DIM);
#pragma unroll
    for (int i = 0; i < 4; i++) {
        const float4 x = xs[i];
        float4 o;
        o.x = x.x + ((q[i].x - mean) * inv - x.x);
        o.y = x.y + ((q[i].y - mean) * inv - x.y);
        o.z = x.z + ((q[i].z - mean) * inv - x.z);
        o.w = x.w + ((q[i].w - mean) * inv - x.w);
        oq[lane + 32 * i] = o;
    }
}

// ---------------- kernel: deterministic diversity reduction (R12 exact) ------
__global__ __launch_bounds__(256)
void vq_div_reduce() {
    const int k = blockIdx.x * 256 + threadIdx.x;  // 0..2047 (gridDim.x = 8)
    const int chunk = blockIdx.y;                  // 0..15
    const int b0 = chunk * 64;
    float s0 = 0.f, s1 = 0.f, s2 = 0.f, s3 = 0.f;
    for (int b = 0; b < 64; b += 4) {
        s0 += g_div_part[(size_t)(b0 + b + 0) * K_CENT + k];
        s1 += g_div_part[(size_t)(b0 + b + 1) * K_CENT + k];
        s2 += g_div_part[(size_t)(b0 + b + 2) * K_CENT + k];
        s3 += g_div_part[(size_t)(b0 + b + 3) * K_CENT + k];
    }
    g_div2[chunk * K_CENT + k] = (s0 + s1) + (s2 + s3);
}

// ---------------- kernel: finalize loss only (no counts dependency) ----------
// Arithmetic for hdiv/hsum identical to the fused R12 finalize -> g_loss bit-exact.
__global__ __launch_bounds__(256)
void vq_finalize_loss() {
    __shared__ float redf[256];
    const int t = threadIdx.x;

    float hdiv = 0.f;
    for (int k = t; k < K_CENT; k += 256) {
        float s = 0.f;
#pragma unroll
        for (int ch = 0; ch < 16; ch++) s += g_div2[ch * K_CENT + k];
        float d = s * (1.0f / (float)N_ROWS);
        hdiv += d * __log2f(d + EPSF);
    }
    float hsum = 0.f;
    for (int i = t; i < NBLK_SM; i += 256) hsum += g_h_part[i];

    redf[t] = hdiv;
    __syncthreads();
    for (int s = 128; s > 0; s >>= 1) { if (t < s) redf[t] += redf[t + s]; __syncthreads(); }
    const float hdiv_tot = redf[0];
    __syncthreads();
    redf[t] = hsum;
    __syncthreads();
    for (int s = 128; s > 0; s >>= 1) { if (t < s) redf[t] += redf[t + s]; __syncthreads(); }
    if (t == 0) {
        float h_clust     = -(redf[0] / (float)N_ROWS);
        float h_diversity = -hdiv_tot;
        g_loss = h_clust - GAMMAF * h_diversity;
    }
}

// ---------------- kernel: EMA counts (elementwise, after refine) --------------
__global__ __launch_bounds__(256)
void vq_ema(const float* __restrict__ cluster_counts,
            const int* __restrict__ train,
            float* __restrict__ out_counts) {
    const int k = blockIdx.x * 256 + threadIdx.x;
    if (k >= K_CENT) return;
    const int tr = train[0];
    float cnt = (float)g_counts[k];
    float oc  = cluster_counts[k];
    out_counts[k] = tr ? (EMA * oc + (1.0f - EMA) * cnt) : oc;
}

// ---------------- kernel: loss broadcast-fill + codebook copy (fused) --------
__global__ __launch_bounds__(256)
void vq_fill(float* __restrict__ loss_dst, float* __restrict__ cb_dst,
             const float* __restrict__ cb_src) {
    const int b = blockIdx.x;
    const int t = threadIdx.x;
    if (b < 2048) {
        const float v = g_loss;
        const float4 f = make_float4(v, v, v, v);
        float4* dst = (float4*)loss_dst + (size_t)b * 4096 + t;
#pragma unroll
        for (int j = 0; j < 16; j++)
            dst[j * 256] = f;
    } else {
        const size_t base = (size_t)(b - 2048) * 4096 + t;
        const float4* src = (const float4*)cb_src;
        float4* dst = (float4*)cb_dst;
#pragma unroll
        for (int j = 0; j < 16; j++)
            dst[base + j * 256] = src[base + j * 256];
    }
}

// ---------------- launcher: loss chain ∥ (refine -> ema) ----------------------
extern "C" void kernel_launch(void* const* d_in, const int* in_sizes, int n_in,
                              void* d_out, int out_size) {
    const float* inputs   = (const float*)d_in[0];
    const float* codebook = (const float*)d_in[1];
    const float* ccounts  = (const float*)d_in[2];
    const int*   train    = (const int*)d_in[3];
    float* out = (float*)d_out;

    static bool inited = false;
    static cudaStream_t s2;
    static cudaEvent_t evS, evE;
    if (!inited) {
        cudaFuncSetAttribute(vq_gemm_mma, cudaFuncAttributeMaxDynamicSharedMemorySize, GSM_TOTAL);
        cudaStreamCreateWithFlags(&s2, cudaStreamNonBlocking);
        cudaEventCreateWithFlags(&evS, cudaEventDisableTiming);
        cudaEventCreateWithFlags(&evE, cudaEventDisableTiming);
        inited = true;
    }

    vq_convert<<<9216, 256>>>(inputs, codebook);   // also resets g_ncand/g_counts
    vq_gemm_mma<<<dim3(K_CENT / GBN, N_ROWS / GBM), 256, GSM_TOTAL>>>();
    vq_softmax<<<NBLK_SM, 256>>>();
    cudaEventRecord(evS, 0);

    // fork s2: refine (argmax + quantize + counts) then EMA counts
    cudaStreamWaitEvent(s2, evS, 0);
    vq_refine<<<N_ROWS / 8, 256, 0, s2>>>(inputs, codebook, out + OFF_IDX, out + OFF_Q);
    vq_ema<<<8, 256, 0, s2>>>(ccounts, train, out + OFF_CNT);
    cudaEventRecord(evE, s2);

    // main chain: loss (independent of counts) + big fill, overlapping refine
    vq_div_reduce<<<dim3(8, 16), 256>>>();
    vq_finalize_loss<<<1, 256>>>();
    vq_fill<<<2112, 256>>>(out + OFF_LOSS, out + OFF_CB, codebook);

    cudaStreamWaitEvent(0, evE, 0);                // join
    (void)in_sizes; (void)n_in; (void)out_size;
}